// round 8
// baseline (speedup 1.0000x reference)
#include <cuda_runtime.h>
#include <cuda_bf16.h>
#include <math.h>
#include <stdint.h>

#define B_ 4
#define T_ 1024
#define F_ 128
#define D_ 512
#define H_ 8
#define L_ 4
#define DFF_ 2048
#define MD_ 20
#define HD_ 64
#define NT_ (B_*T_)
#define SCALE_ 0.125f
#define LOG2E_ 1.4426950408889634f
#define SC2_ (SCALE_*LOG2E_)

// ---------------- scratch (device globals: no allocations allowed) ----------
__device__ float g_x  [NT_*(size_t)D_];
__device__ float g_q  [NT_*(size_t)D_];
__device__ float g_k  [NT_*(size_t)D_];
__device__ float g_v  [NT_*(size_t)D_];
__device__ float g_o  [NT_*(size_t)D_];
__device__ float g_ffn[NT_*(size_t)DFF_];
__device__ __nv_bfloat16 g_biash[(size_t)B_*H_*T_*T_];   // bias * log2(e), bf16

// ---------------- tf32 helpers ----------------------------------------------
__device__ __forceinline__ float to_tf32(float x) {
    float y; asm("cvt.rna.tf32.f32 %0, %1;" : "=f"(y) : "f"(x)); return y;
}
__device__ __forceinline__ float4 cvt4(float4 v) {
    v.x = to_tf32(v.x); v.y = to_tf32(v.y); v.z = to_tf32(v.z); v.w = to_tf32(v.w);
    return v;
}
__device__ __forceinline__ float ex2(float x) {
    float y; asm("ex2.approx.f32 %0, %1;" : "=f"(y) : "f"(x)); return y;
}
// D += A(16x8,row) * B(8x8,col);  A,B hold tf32 bit patterns in fp32 regs.
__device__ __forceinline__ void mma8(float* d, const float* a, const float* b) {
    asm volatile(
      "mma.sync.aligned.m16n8k8.row.col.f32.tf32.tf32.f32 "
      "{%0,%1,%2,%3}, {%4,%5,%6,%7}, {%8,%9}, {%0,%1,%2,%3};\n"
      : "+f"(d[0]), "+f"(d[1]), "+f"(d[2]), "+f"(d[3])
      : "r"(__float_as_uint(a[0])), "r"(__float_as_uint(a[1])),
        "r"(__float_as_uint(a[2])), "r"(__float_as_uint(a[3])),
        "r"(__float_as_uint(b[0])), "r"(__float_as_uint(b[1])));
}

__device__ __forceinline__ float warp_red_sum(float v) {
    #pragma unroll
    for (int o = 16; o > 0; o >>= 1) v += __shfl_xor_sync(0xffffffffu, v, o);
    return v;
}

// ---------------- tf32 GEMM: C[M=4096, N] = act(A[M,K] @ W[K,N] + bias) -----
// 128x128x32 block tile, 256 threads, warp tile 64x32 (m16n8k8 frags).
// Two-stage smem double buffer, one __syncthreads per K-chunk.
// __launch_bounds__(256, 2): cap 128 regs -> 2 CTAs/SM (16 warps) so LDS-frag
// issue and tensor issue interleave across CTAs.
#define AS_ELEMS (128*36)
#define BS_ELEMS (32*136)
#define GEMM_SMEM ((2*(AS_ELEMS + BS_ELEMS))*4)   // 71680 B

struct GemmP {
    const float* A;
    const float* W[3];
    const float* bias[3];
    float*       C[3];
    const float* resid;
    int K, N;
};

template<int ACT, bool RESID>
__global__ __launch_bounds__(256, 2)
void gemm_tf32(GemmP p)
{
    extern __shared__ float sm[];
    float* Asb = sm;                       // [2][128*36]
    float* Bsb = sm + 2*AS_ELEMS;          // [2][32*136]

    const int z = blockIdx.z;
    const float* __restrict__ A    = p.A;
    const float* __restrict__ W    = p.W[z];
    const float* __restrict__ bias = p.bias[z];
    float*       __restrict__ C    = p.C[z];
    const float* __restrict__ resid = p.resid;
    const int K = p.K, N = p.N;
    const int m0 = blockIdx.y * 128, n0 = blockIdx.x * 128;

    const int tid  = threadIdx.x;
    const int warp = tid >> 5, lane = tid & 31;
    const int g  = lane >> 2, qd = lane & 3;
    const int wm = (warp >> 2) * 64;
    const int wn = (warp & 3)  * 32;

    const int a_m  = tid >> 3;
    const int a_k4 = tid & 7;
    const int b_k  = tid >> 5;
    const int b_n4 = tid & 31;

    float4 ra[4], rb[4];
    float acc[4][4][4];
    #pragma unroll
    for (int i = 0; i < 4; i++)
        #pragma unroll
        for (int j = 0; j < 4; j++)
            #pragma unroll
            for (int u = 0; u < 4; u++) acc[i][j][u] = 0.f;

    const int nk = K >> 5;

    // prologue: chunk 0 -> regs -> smem buf 0
    #pragma unroll
    for (int i = 0; i < 4; i++)
        ra[i] = *(const float4*)&A[(size_t)(m0 + a_m + 32*i) * K + a_k4*4];
    #pragma unroll
    for (int i = 0; i < 4; i++)
        rb[i] = *(const float4*)&W[(size_t)(b_k + 8*i) * N + n0 + b_n4*4];
    #pragma unroll
    for (int i = 0; i < 4; i++) {
        const int m = a_m + 32*i;
        *(float4*)&Asb[m*36 + ((a_k4*4) ^ ((m & 3) << 3))] = cvt4(ra[i]);
    }
    #pragma unroll
    for (int i = 0; i < 4; i++)
        *(float4*)&Bsb[(b_k + 8*i)*136 + b_n4*4] = cvt4(rb[i]);
    __syncthreads();

    // chunk 1 -> regs (in flight during first mma block)
    if (nk > 1) {
        #pragma unroll
        for (int i = 0; i < 4; i++)
            ra[i] = *(const float4*)&A[(size_t)(m0 + a_m + 32*i) * K + 32 + a_k4*4];
        #pragma unroll
        for (int i = 0; i < 4; i++)
            rb[i] = *(const float4*)&W[(size_t)(32 + b_k + 8*i) * N + n0 + b_n4*4];
    }

    for (int kt = 0; kt < nk; kt++) {
        const float* As = Asb + (kt & 1) * AS_ELEMS;
        const float* Bs = Bsb + (kt & 1) * BS_ELEMS;

        #pragma unroll
        for (int kk = 0; kk < 4; kk++) {
            const int kb = kk * 8;
            float afr[4][4], bfr[4][2];
            #pragma unroll
            for (int mi = 0; mi < 4; mi++) {
                const int m_ = wm + mi*16 + g;
                const int sw = (m_ & 3) << 3;
                afr[mi][0] = As[ m_     *36 + ((kb + qd    ) ^ sw)];
                afr[mi][1] = As[(m_ + 8)*36 + ((kb + qd    ) ^ sw)];
                afr[mi][2] = As[ m_     *36 + ((kb + qd + 4) ^ sw)];
                afr[mi][3] = As[(m_ + 8)*36 + ((kb + qd + 4) ^ sw)];
            }
            #pragma unroll
            for (int ni = 0; ni < 4; ni++) {
                const int n_ = wn + ni*8 + g;
                bfr[ni][0] = Bs[(kb + qd    )*136 + n_];
                bfr[ni][1] = Bs[(kb + qd + 4)*136 + n_];
            }
            #pragma unroll
            for (int mi = 0; mi < 4; mi++)
                #pragma unroll
                for (int ni = 0; ni < 4; ni++)
                    mma8(acc[mi][ni], afr[mi], bfr[ni]);
        }

        if (kt + 1 < nk) {
            // stage chunk kt+1 (already in regs) into the other buffer
            float* Asw = Asb + ((kt + 1) & 1) * AS_ELEMS;
            float* Bsw = Bsb + ((kt + 1) & 1) * BS_ELEMS;
            #pragma unroll
            for (int i = 0; i < 4; i++) {
                const int m = a_m + 32*i;
                *(float4*)&Asw[m*36 + ((a_k4*4) ^ ((m & 3) << 3))] = cvt4(ra[i]);
            }
            #pragma unroll
            for (int i = 0; i < 4; i++)
                *(float4*)&Bsw[(b_k + 8*i)*136 + b_n4*4] = cvt4(rb[i]);
            // issue LDG for chunk kt+2
            if (kt + 2 < nk) {
                const int k0 = (kt + 2) << 5;
                #pragma unroll
                for (int i = 0; i < 4; i++)
                    ra[i] = *(const float4*)&A[(size_t)(m0 + a_m + 32*i) * K + k0 + a_k4*4];
                #pragma unroll
                for (int i = 0; i < 4; i++)
                    rb[i] = *(const float4*)&W[(size_t)(k0 + b_k + 8*i) * N + n0 + b_n4*4];
            }
            __syncthreads();
        }
    }

    // epilogue
    #pragma unroll
    for (int mi = 0; mi < 4; mi++) {
        const int r0 = m0 + wm + mi*16 + g;
        #pragma unroll
        for (int ni = 0; ni < 4; ni++) {
            const int c0 = n0 + wn + ni*8 + qd*2;
            const float2 bv = *(const float2*)&bias[c0];
            float v0 = acc[mi][ni][0] + bv.x;
            float v1 = acc[mi][ni][1] + bv.y;
            float v2 = acc[mi][ni][2] + bv.x;
            float v3 = acc[mi][ni][3] + bv.y;
            if (ACT == 1) {
                v0 = v0 / (1.0f + __expf(-v0));
                v1 = v1 / (1.0f + __expf(-v1));
                v2 = v2 / (1.0f + __expf(-v2));
                v3 = v3 / (1.0f + __expf(-v3));
            }
            if (RESID) {
                const float2 r1 = *(const float2*)&resid[(size_t)r0 * N + c0];
                const float2 r2 = *(const float2*)&resid[(size_t)(r0 + 8) * N + c0];
                v0 += r1.x; v1 += r1.y; v2 += r2.x; v3 += r2.y;
            }
            *(float2*)&C[(size_t)r0       * N + c0] = make_float2(v0, v1);
            *(float2*)&C[(size_t)(r0 + 8) * N + c0] = make_float2(v2, v3);
        }
    }
}

// ---------------- fused flash attention v2 (tf32) ---------------------------
// Grid (T/64, B*H), 128 threads = 4 warps; warp owns 16 q-rows x full 64-col
// j tile -> warp-local online softmax. Q frags live in REGISTERS.
#define FL_SMEM (53248)

__global__ __launch_bounds__(128, 4)
void flash_tf32(const float* __restrict__ q, const float* __restrict__ k,
                const float* __restrict__ v,
                const __nv_bfloat16* __restrict__ biash,
                float* __restrict__ o)
{
    extern __shared__ char smem_raw[];
    float* Ks = (float*)smem_raw;                 // [64][68]
    float* Vs = Ks + 64*68;                       // [64][72]
    float* Ps = Vs + 64*72;                       // [64][68] swizzled (union w/ bias)
    __nv_bfloat16* Bb = (__nv_bfloat16*)Ps;       // bias: warp w rows at w*2176 + (r&15)*72

    const int z = blockIdx.y;
    const int b = z >> 3, h = z & 7;
    const int i0 = blockIdx.x * 64;
    const float* qp = q + (size_t)b*T_*D_ + h*HD_;
    const float* kp = k + (size_t)b*T_*D_ + h*HD_;
    const float* vp = v + (size_t)b*T_*D_ + h*HD_;
    const __nv_bfloat16* bp = biash + (size_t)z*T_*T_;

    const int tid = threadIdx.x;
    const int warp = tid >> 5, lane = tid & 31;
    const int g = lane >> 2, qd = lane & 3;
    const int slab = warp * 16;
    const int sw = (g & 3) << 3;          // swizzle for rows slab+g, slab+g+8
    float* Pw = Ps + warp * 1088;         // this warp's P slab [16][68]

    // stage Q through Ps once, lift this warp's frags into registers
    #pragma unroll
    for (int u = 0; u < 8; u++) {
        const int idx = u*128 + tid;
        const int r = idx >> 4, d4 = idx & 15;
        float4 val = cvt4(*(const float4*)&qp[(size_t)(i0 + r)*D_ + d4*4]);
        *(float4*)&Ps[r*68 + ((d4*4) ^ ((r & 3) << 3))] = val;
    }
    __syncthreads();
    float qf[8][4];
    #pragma unroll
    for (int kk = 0; kk < 8; kk++) {
        const int kb = kk * 8;
        const int mr = slab + g;
        qf[kk][0] = Ps[ mr     *68 + ((kb + qd    ) ^ sw)];
        qf[kk][1] = Ps[(mr + 8)*68 + ((kb + qd    ) ^ sw)];
        qf[kk][2] = Ps[ mr     *68 + ((kb + qd + 4) ^ sw)];
        qf[kk][3] = Ps[(mr + 8)*68 + ((kb + qd + 4) ^ sw)];
    }
    // first loop iteration begins with __syncthreads -> safe to reuse Ps

    float m0 = -1e30f, m1 = -1e30f, l0 = 0.f, l1 = 0.f;
    float oacc[8][4];
    #pragma unroll
    for (int n = 0; n < 8; n++)
        #pragma unroll
        for (int u = 0; u < 4; u++) oacc[n][u] = 0.f;

    for (int jt = 0; jt < T_/64; jt++) {
        const int j0 = jt * 64;
        __syncthreads();   // prev iter's PV done with Vs/Ps; safe to overwrite
        #pragma unroll
        for (int u = 0; u < 8; u++) {
            const int idx = u*128 + tid;
            const int r = idx >> 4, d4 = idx & 15;
            *(float4*)&Ks[r*68 + d4*4] = cvt4(*(const float4*)&kp[(size_t)(j0 + r)*D_ + d4*4]);
            *(float4*)&Vs[r*72 + d4*4] = cvt4(*(const float4*)&vp[(size_t)(j0 + r)*D_ + d4*4]);
        }
        #pragma unroll
        for (int u = 0; u < 4; u++) {      // bias: 64 rows x 8 uint4
            const int idx = u*128 + tid;
            const int br = idx >> 3, seg = idx & 7;
            *(uint4*)&Bb[(br >> 4)*2176 + (br & 15)*72 + seg*8] =
                *(const uint4*)&bp[(size_t)(i0 + br)*T_ + j0 + seg*8];
        }
        __syncthreads();

        // S = Q K^T (Q frags from registers)
        float sacc[8][4];
        #pragma unroll
        for (int n = 0; n < 8; n++)
            #pragma unroll
            for (int u = 0; u < 4; u++) sacc[n][u] = 0.f;
        #pragma unroll
        for (int kk = 0; kk < 8; kk++) {
            const int kb = kk * 8;
            #pragma unroll
            for (int n = 0; n < 8; n++) {
                const int nr = n*8 + g;
                float bfr[2];
                bfr[0] = Ks[nr*68 + kb + qd];
                bfr[1] = Ks[nr*68 + kb + qd + 4];
                mma8(sacc[n], qf[kk], bfr);
            }
        }

        // epilogue: s2 = sacc*SC2 + bias2 (log2 domain), online softmax
        float sv[8][4];
        float mx0 = -1e30f, mx1 = -1e30f;
        #pragma unroll
        for (int n = 0; n < 8; n++) {
            const int c = n*8 + qd*2;
            const float2 bv0 = __bfloat1622float2(*(const __nv_bfloat162*)&Bb[warp*2176 + g    *72 + c]);
            const float2 bv1 = __bfloat1622float2(*(const __nv_bfloat162*)&Bb[warp*2176 + (g+8)*72 + c]);
            sv[n][0] = fmaf(sacc[n][0], SC2_, bv0.x);
            sv[n][1] = fmaf(sacc[n][1], SC2_, bv0.y);
            sv[n][2] = fmaf(sacc[n][2], SC2_, bv1.x);
            sv[n][3] = fmaf(sacc[n][3], SC2_, bv1.y);
            mx0 = fmaxf(mx0, fmaxf(sv[n][0], sv[n][1]));
            mx1 = fmaxf(mx1, fmaxf(sv[n][2], sv[n][3]));
        }
        mx0 = fmaxf(mx0, __shfl_xor_sync(0xffffffffu, mx0, 1));
        mx0 = fmaxf(mx0, __shfl_xor_sync(0xffffffffu, mx0, 2));
        mx1 = fmaxf(mx1, __shfl_xor_sync(0xffffffffu, mx1, 1));
        mx1 = fmaxf(mx1, __shfl_xor_sync(0xffffffffu, mx1, 2));

        __syncwarp();      // all bias-frag reads in this warp done before P writes

        const float mn0 = fmaxf(m0, mx0), mn1 = fmaxf(m1, mx1);
        const float al0 = ex2(m0 - mn0),  al1 = ex2(m1 - mn1);
        float rs0 = 0.f, rs1 = 0.f;
        #pragma unroll
        for (int n = 0; n < 8; n++) {
            const float p0 = ex2(sv[n][0] - mn0);
            const float p1 = ex2(sv[n][1] - mn0);
            const float p2 = ex2(sv[n][2] - mn1);
            const float p3 = ex2(sv[n][3] - mn1);
            rs0 += p0 + p1; rs1 += p2 + p3;
            const int c = (n*8 + qd*2) ^ sw;
            *(float2*)&Pw[ g    *68 + c] = make_float2(to_tf32(p0), to_tf32(p1));
            *(float2*)&Pw[(g+8)*68 + c] = make_float2(to_tf32(p2), to_tf32(p3));
            oacc[n][0] *= al0; oacc[n][1] *= al0;
            oacc[n][2] *= al1; oacc[n][3] *= al1;
        }
        rs0 += __shfl_xor_sync(0xffffffffu, rs0, 1);
        rs0 += __shfl_xor_sync(0xffffffffu, rs0, 2);
        rs1 += __shfl_xor_sync(0xffffffffu, rs1, 1);
        rs1 += __shfl_xor_sync(0xffffffffu, rs1, 2);
        l0 = l0*al0 + rs0;  m0 = mn0;
        l1 = l1*al1 + rs1;  m1 = mn1;

        __syncwarp();      // P rows warp-private; intra-warp visibility only

        // O += P @ V
        #pragma unroll
        for (int kk = 0; kk < 8; kk++) {
            const int kb = kk * 8;
            float afr[4];
            afr[0] = Pw[ g    *68 + ((kb + qd    ) ^ sw)];
            afr[1] = Pw[(g+8)*68 + ((kb + qd    ) ^ sw)];
            afr[2] = Pw[ g    *68 + ((kb + qd + 4) ^ sw)];
            afr[3] = Pw[(g+8)*68 + ((kb + qd + 4) ^ sw)];
            #pragma unroll
            for (int n = 0; n < 8; n++) {
                float bfr[2];
                bfr[0] = Vs[(kb + qd    )*72 + n*8 + g];
                bfr[1] = Vs[(kb + qd + 4)*72 + n*8 + g];
                mma8(oacc[n], afr, bfr);
            }
        }
    }

    const float inv0 = 1.0f / l0, inv1 = 1.0f / l1;
    const size_t r0 = (size_t)b*T_ + i0 + slab + g;
    #pragma unroll
    for (int n = 0; n < 8; n++) {
        const int c = h*HD_ + n*8 + qd*2;
        *(float2*)&o[ r0      * D_ + c] = make_float2(oacc[n][0]*inv0, oacc[n][1]*inv0);
        *(float2*)&o[(r0 + 8) * D_ + c] = make_float2(oacc[n][2]*inv1, oacc[n][3]*inv1);
    }
}

// ---------------- embedding extras ------------------------------------------
__global__ void add_cent_kernel(float* __restrict__ h, const float* __restrict__ cent,
                                const float* __restrict__ cw, const float* __restrict__ cb)
{
    const int n = blockIdx.x, d = threadIdx.x;
    h[(size_t)n * D_ + d] += cent[n] * cw[d] + cb[d];
}

// biash[b,h,i,j] = (edge_emb[et,h] + dist_emb[sp,h]) * log2(e)  as bf16
// vectorized: each thread handles 4 consecutive j -> int4 loads, 8B stores.
__global__ __launch_bounds__(256)
void bias_kernel(const int* __restrict__ et, const int* __restrict__ sp,
                 const float* __restrict__ ee, const float* __restrict__ de,
                 __nv_bfloat16* __restrict__ bias)
{
    const size_t t4   = (size_t)blockIdx.x * blockDim.x + threadIdx.x;  // B*T*T/4
    const size_t base = t4 * 4;
    const int4 e4 = *(const int4*)&et[base];
    int4 s4 = *(const int4*)&sp[base];
    s4.x = min(max(s4.x, 0), MD_); s4.y = min(max(s4.y, 0), MD_);
    s4.z = min(max(s4.z, 0), MD_); s4.w = min(max(s4.w, 0), MD_);
    const size_t j = base & (T_ - 1);
    const size_t i = (base >> 10) & (T_ - 1);
    const size_t b = base >> 20;
    #pragma unroll
    for (int hh = 0; hh < H_; hh++) {
        __nv_bfloat16 o0 = __float2bfloat16((ee[e4.x*H_ + hh] + de[s4.x*H_ + hh]) * LOG2E_);
        __nv_bfloat16 o1 = __float2bfloat16((ee[e4.y*H_ + hh] + de[s4.y*H_ + hh]) * LOG2E_);
        __nv_bfloat16 o2 = __float2bfloat16((ee[e4.z*H_ + hh] + de[s4.z*H_ + hh]) * LOG2E_);
        __nv_bfloat16 o3 = __float2bfloat16((ee[e4.w*H_ + hh] + de[s4.w*H_ + hh]) * LOG2E_);
        __nv_bfloat162 p01 = __halves2bfloat162(o0, o1);
        __nv_bfloat162 p23 = __halves2bfloat162(o2, o3);
        uint2 pk;
        pk.x = *(uint32_t*)&p01;
        pk.y = *(uint32_t*)&p23;
        *(uint2*)&bias[(((b*H_ + hh)*T_ + i)*T_) + j] = pk;
    }
}

// ---------------- layernorm --------------------------------------------------
__global__ __launch_bounds__(128)
void ln_kernel(const float* __restrict__ h, const float* __restrict__ w,
               const float* __restrict__ b, float* __restrict__ out)
{
    __shared__ float red[8];
    const int t = threadIdx.x;
    const float* hp = h + (size_t)blockIdx.x * D_;
    float v[4]; float s = 0.f, s2 = 0.f;
    #pragma unroll
    for (int u = 0; u < 4; u++) { v[u] = hp[t + u*128]; s += v[u]; s2 += v[u]*v[u]; }
    s  = warp_red_sum(s);
    s2 = warp_red_sum(s2);
    if ((t & 31) == 0) { red[t>>5] = s; red[4 + (t>>5)] = s2; }
    __syncthreads();
    s  = red[0] + red[1] + red[2] + red[3];
    s2 = red[4] + red[5] + red[6] + red[7];
    const float m   = s  * (1.0f / D_);
    const float var = s2 * (1.0f / D_) - m * m;
    const float r   = rsqrtf(var + 1e-5f);
    float* op = out + (size_t)blockIdx.x * D_;
    #pragma unroll
    for (int u = 0; u < 4; u++) {
        const int d = t + u*128;
        op[d] = (v[u] - m) * r * w[d] + b[d];
    }
}

// ---------------- host-side orchestration -----------------------------------
static inline void gemm1(const float* A, const float* W, const float* bias,
                         const float* resid, float* C, int K, int N, int act)
{
    GemmP p;
    p.A = A;
    p.W[0] = p.W[1] = p.W[2] = W;
    p.bias[0] = p.bias[1] = p.bias[2] = bias;
    p.C[0] = p.C[1] = p.C[2] = C;
    p.resid = resid;
    p.K = K; p.N = N;
    dim3 g(N / 128, NT_ / 128, 1);
    if (act == 1)        gemm_tf32<1,false><<<g,256,GEMM_SMEM>>>(p);
    else if (resid)      gemm_tf32<0,true ><<<g,256,GEMM_SMEM>>>(p);
    else                 gemm_tf32<0,false><<<g,256,GEMM_SMEM>>>(p);
}

extern "C" void kernel_launch(void* const* d_in, const int* in_sizes, int n_in,
                              void* d_out, int out_size)
{
    const float* nf     = (const float*)d_in[0];
    const float* cent   = (const float*)d_in[1];
    const int*   et     = (const int*)  d_in[2];
    const int*   sp     = (const int*)  d_in[3];
    const float* node_W = (const float*)d_in[4];
    const float* node_b = (const float*)d_in[5];
    const float* cent_W = (const float*)d_in[6];
    const float* cent_b = (const float*)d_in[7];
    const float* e_emb  = (const float*)d_in[8];
    const float* d_emb  = (const float*)d_in[9];
    const float* ln1w   = (const float*)d_in[10];
    const float* ln1b   = (const float*)d_in[11];
    const float* qW     = (const float*)d_in[12];
    const float* qb     = (const float*)d_in[13];
    const float* kW     = (const float*)d_in[14];
    const float* kb     = (const float*)d_in[15];
    const float* vW     = (const float*)d_in[16];
    const float* vb     = (const float*)d_in[17];
    const float* oW     = (const float*)d_in[18];
    const float* ob     = (const float*)d_in[19];
    const float* ln2w   = (const float*)d_in[20];
    const float* ln2b   = (const float*)d_in[21];
    const float* f1W    = (const float*)d_in[22];
    const float* f1b    = (const float*)d_in[23];
    const float* f2W    = (const float*)d_in[24];
    const float* f2b    = (const float*)d_in[25];

    float* h = (float*)d_out;

    float *px, *pq, *pk, *pv, *po, *pffn;
    __nv_bfloat16* pbias;
    cudaGetSymbolAddress((void**)&px,    g_x);
    cudaGetSymbolAddress((void**)&pq,    g_q);
    cudaGetSymbolAddress((void**)&pk,    g_k);
    cudaGetSymbolAddress((void**)&pv,    g_v);
    cudaGetSymbolAddress((void**)&po,    g_o);
    cudaGetSymbolAddress((void**)&pffn,  g_ffn);
    cudaGetSymbolAddress((void**)&pbias, g_biash);

    cudaFuncSetAttribute(flash_tf32, cudaFuncAttributeMaxDynamicSharedMemorySize, FL_SMEM);
    cudaFuncSetAttribute(gemm_tf32<0,false>, cudaFuncAttributeMaxDynamicSharedMemorySize, GEMM_SMEM);
    cudaFuncSetAttribute(gemm_tf32<0,true >, cudaFuncAttributeMaxDynamicSharedMemorySize, GEMM_SMEM);
    cudaFuncSetAttribute(gemm_tf32<1,false>, cudaFuncAttributeMaxDynamicSharedMemorySize, GEMM_SMEM);

    // embedding: h = nf @ node_W + node_b ; h += cent*cent_W + cent_b
    gemm1(nf, node_W, node_b, nullptr, h, F_, D_, 0);
    add_cent_kernel<<<NT_, D_>>>(h, cent, cent_W, cent_b);

    // Graphormer attention bias (layer-invariant), bf16, log2e pre-folded
    bias_kernel<<<(B_*T_*T_)/(256*4), 256>>>(et, sp, e_emb, d_emb, pbias);

    for (int l = 0; l < L_; l++) {
        const size_t wd = (size_t)l * D_ * D_;
        // x = LN1(h)
        ln_kernel<<<NT_, 128>>>(h, ln1w + l*D_, ln1b + l*D_, px);
        // q,k,v in one batched launch (grid.z = 3)
        {
            GemmP p;
            p.A = px;
            p.W[0] = qW + wd;  p.W[1] = kW + wd;  p.W[2] = vW + wd;
            p.bias[0] = qb + l*D_; p.bias[1] = kb + l*D_; p.bias[2] = vb + l*D_;
            p.C[0] = pq; p.C[1] = pk; p.C[2] = pv;
            p.resid = nullptr;
            p.K = D_; p.N = D_;
            gemm_tf32<0,false><<<dim3(D_/128, NT_/128, 3), 256, GEMM_SMEM>>>(p);
        }
        // fused attention: scores + softmax + AV, no global scores
        flash_tf32<<<dim3(T_/64, B_*H_), 128, FL_SMEM>>>(pq, pk, pv, pbias, po);
        // h += o @ oW + ob
        gemm1(po, oW + wd, ob + l*D_, h, h, D_, D_, 0);
        // FFN
        ln_kernel<<<NT_, 128>>>(h, ln2w + l*D_, ln2b + l*D_, px);
        gemm1(px,   f1W + (size_t)l*D_*DFF_, f1b + l*DFF_, nullptr, pffn, D_,   DFF_, 1);
        gemm1(pffn, f2W + (size_t)l*DFF_*D_, f2b + l*D_,   h,       h,    DFF_, D_,   0);
    }
}

// round 10
// speedup vs baseline: 1.0225x; 1.0225x over previous
#include <cuda_runtime.h>
#include <cuda_bf16.h>
#include <math.h>
#include <stdint.h>

#define B_ 4
#define T_ 1024
#define F_ 128
#define D_ 512
#define H_ 8
#define L_ 4
#define DFF_ 2048
#define MD_ 20
#define HD_ 64
#define NT_ (B_*T_)
#define SCALE_ 0.125f
#define LOG2E_ 1.4426950408889634f
#define SC2_ (SCALE_*LOG2E_)

// ---------------- scratch (device globals: no allocations allowed) ----------
__device__ float g_x  [NT_*(size_t)D_];
__device__ float g_q  [NT_*(size_t)D_];
__device__ float g_k  [NT_*(size_t)D_];
__device__ float g_v  [NT_*(size_t)D_];
__device__ float g_o  [NT_*(size_t)D_];
__device__ float g_ffn[NT_*(size_t)DFF_];
__device__ __nv_bfloat16 g_biash[(size_t)B_*H_*T_*T_];   // bias * log2(e), bf16

// ---------------- tf32 helpers ----------------------------------------------
__device__ __forceinline__ float to_tf32(float x) {
    float y; asm("cvt.rna.tf32.f32 %0, %1;" : "=f"(y) : "f"(x)); return y;
}
__device__ __forceinline__ float4 cvt4(float4 v) {
    v.x = to_tf32(v.x); v.y = to_tf32(v.y); v.z = to_tf32(v.z); v.w = to_tf32(v.w);
    return v;
}
__device__ __forceinline__ float ex2(float x) {
    float y; asm("ex2.approx.f32 %0, %1;" : "=f"(y) : "f"(x)); return y;
}
// D += A(16x8,row) * B(8x8,col);  A,B hold tf32 bit patterns in fp32 regs.
__device__ __forceinline__ void mma8(float* d, const float* a, const float* b) {
    asm volatile(
      "mma.sync.aligned.m16n8k8.row.col.f32.tf32.tf32.f32 "
      "{%0,%1,%2,%3}, {%4,%5,%6,%7}, {%8,%9}, {%0,%1,%2,%3};\n"
      : "+f"(d[0]), "+f"(d[1]), "+f"(d[2]), "+f"(d[3])
      : "r"(__float_as_uint(a[0])), "r"(__float_as_uint(a[1])),
        "r"(__float_as_uint(a[2])), "r"(__float_as_uint(a[3])),
        "r"(__float_as_uint(b[0])), "r"(__float_as_uint(b[1])));
}

__device__ __forceinline__ float warp_red_sum(float v) {
    #pragma unroll
    for (int o = 16; o > 0; o >>= 1) v += __shfl_xor_sync(0xffffffffu, v, o);
    return v;
}

// ---------------- tf32 GEMM v3: 512 threads, 32x32 warp tile -----------------
// C[M=4096, N] = act(A[M,K] @ W[K,N] + bias) (+resid)
// 128x128x32 block tile, 16 warps, warp tile 32x32 (2x4 m16n8k8 frags).
// ~80 regs/thread -> no spills, 16 warps/SM. Two-stage smem double buffer,
// one __syncthreads per K-chunk; LDG of chunk kt+2 in flight during mma of kt.
#define AS_ELEMS (128*36)
#define BS_ELEMS (32*136)
#define GEMM_SMEM ((2*(AS_ELEMS + BS_ELEMS))*4)   // 71680 B

struct GemmP {
    const float* A;
    const float* W[3];
    const float* bias[3];
    float*       C[3];
    const float* resid;
    int K, N;
};

template<int ACT, bool RESID>
__global__ __launch_bounds__(512)
void gemm_tf32(GemmP p)
{
    extern __shared__ float sm[];
    float* Asb = sm;                       // [2][128*36]
    float* Bsb = sm + 2*AS_ELEMS;          // [2][32*136]

    const int z = blockIdx.z;
    const float* __restrict__ A    = p.A;
    const float* __restrict__ W    = p.W[z];
    const float* __restrict__ bias = p.bias[z];
    float*       __restrict__ C    = p.C[z];
    const float* __restrict__ resid = p.resid;
    const int K = p.K, N = p.N;
    const int m0 = blockIdx.y * 128, n0 = blockIdx.x * 128;

    const int tid  = threadIdx.x;
    const int warp = tid >> 5, lane = tid & 31;
    const int g  = lane >> 2, qd = lane & 3;
    const int wm = (warp >> 2) * 32;       // 0,32,64,96
    const int wn = (warp & 3)  * 32;       // 0,32,64,96

    float4 ra[2], rb[2];
    float acc[2][4][4];
    #pragma unroll
    for (int i = 0; i < 2; i++)
        #pragma unroll
        for (int j = 0; j < 4; j++)
            #pragma unroll
            for (int u = 0; u < 4; u++) acc[i][j][u] = 0.f;

    const int nk = K >> 5;

    // prologue: chunk 0 -> regs -> smem buf 0
    #pragma unroll
    for (int i = 0; i < 2; i++) {
        const int idx = tid + 512*i;
        ra[i] = *(const float4*)&A[(size_t)(m0 + (idx >> 3)) * K + (idx & 7)*4];
        rb[i] = *(const float4*)&W[(size_t)(idx >> 5) * N + n0 + (idx & 31)*4];
    }
    #pragma unroll
    for (int i = 0; i < 2; i++) {
        const int idx = tid + 512*i;
        const int am = idx >> 3, ak4 = idx & 7;
        *(float4*)&Asb[am*36 + ((ak4*4) ^ ((am & 3) << 3))] = cvt4(ra[i]);
        *(float4*)&Bsb[(idx >> 5)*136 + (idx & 31)*4] = cvt4(rb[i]);
    }
    __syncthreads();

    // chunk 1 -> regs (in flight during first mma block)
    if (nk > 1) {
        #pragma unroll
        for (int i = 0; i < 2; i++) {
            const int idx = tid + 512*i;
            ra[i] = *(const float4*)&A[(size_t)(m0 + (idx >> 3)) * K + 32 + (idx & 7)*4];
            rb[i] = *(const float4*)&W[(size_t)(32 + (idx >> 5)) * N + n0 + (idx & 31)*4];
        }
    }

    for (int kt = 0; kt < nk; kt++) {
        const float* As = Asb + (kt & 1) * AS_ELEMS;
        const float* Bs = Bsb + (kt & 1) * BS_ELEMS;

        #pragma unroll
        for (int kk = 0; kk < 4; kk++) {
            const int kb = kk * 8;
            float afr[2][4], bfr[4][2];
            #pragma unroll
            for (int mi = 0; mi < 2; mi++) {
                const int m_ = wm + mi*16 + g;
                const int sw = (m_ & 3) << 3;
                afr[mi][0] = As[ m_     *36 + ((kb + qd    ) ^ sw)];
                afr[mi][1] = As[(m_ + 8)*36 + ((kb + qd    ) ^ sw)];
                afr[mi][2] = As[ m_     *36 + ((kb + qd + 4) ^ sw)];
                afr[mi][3] = As[(m_ + 8)*36 + ((kb + qd + 4) ^ sw)];
            }
            #pragma unroll
            for (int ni = 0; ni < 4; ni++) {
                const int n_ = wn + ni*8 + g;
                bfr[ni][0] = Bs[(kb + qd    )*136 + n_];
                bfr[ni][1] = Bs[(kb + qd + 4)*136 + n_];
            }
            #pragma unroll
            for (int mi = 0; mi < 2; mi++)
                #pragma unroll
                for (int ni = 0; ni < 4; ni++)
                    mma8(acc[mi][ni], afr[mi], bfr[ni]);
        }

        if (kt + 1 < nk) {
            // stage chunk kt+1 (already in regs) into the other buffer
            float* Asw = Asb + ((kt + 1) & 1) * AS_ELEMS;
            float* Bsw = Bsb + ((kt + 1) & 1) * BS_ELEMS;
            #pragma unroll
            for (int i = 0; i < 2; i++) {
                const int idx = tid + 512*i;
                const int am = idx >> 3, ak4 = idx & 7;
                *(float4*)&Asw[am*36 + ((ak4*4) ^ ((am & 3) << 3))] = cvt4(ra[i]);
                *(float4*)&Bsw[(idx >> 5)*136 + (idx & 31)*4] = cvt4(rb[i]);
            }
            // issue LDG for chunk kt+2
            if (kt + 2 < nk) {
                const int k0 = (kt + 2) << 5;
                #pragma unroll
                for (int i = 0; i < 2; i++) {
                    const int idx = tid + 512*i;
                    ra[i] = *(const float4*)&A[(size_t)(m0 + (idx >> 3)) * K + k0 + (idx & 7)*4];
                    rb[i] = *(const float4*)&W[(size_t)(k0 + (idx >> 5)) * N + n0 + (idx & 31)*4];
                }
            }
            __syncthreads();
        }
    }

    // epilogue
    #pragma unroll
    for (int mi = 0; mi < 2; mi++) {
        const int r0 = m0 + wm + mi*16 + g;
        #pragma unroll
        for (int ni = 0; ni < 4; ni++) {
            const int c0 = n0 + wn + ni*8 + qd*2;
            const float2 bv = *(const float2*)&bias[c0];
            float v0 = acc[mi][ni][0] + bv.x;
            float v1 = acc[mi][ni][1] + bv.y;
            float v2 = acc[mi][ni][2] + bv.x;
            float v3 = acc[mi][ni][3] + bv.y;
            if (ACT == 1) {
                v0 = v0 / (1.0f + __expf(-v0));
                v1 = v1 / (1.0f + __expf(-v1));
                v2 = v2 / (1.0f + __expf(-v2));
                v3 = v3 / (1.0f + __expf(-v3));
            }
            if (RESID) {
                const float2 r1 = *(const float2*)&resid[(size_t)r0 * N + c0];
                const float2 r2 = *(const float2*)&resid[(size_t)(r0 + 8) * N + c0];
                v0 += r1.x; v1 += r1.y; v2 += r2.x; v3 += r2.y;
            }
            *(float2*)&C[(size_t)r0       * N + c0] = make_float2(v0, v1);
            *(float2*)&C[(size_t)(r0 + 8) * N + c0] = make_float2(v2, v3);
        }
    }
}

// ---------------- fused flash attention v2 (tf32) ---------------------------
// Grid (T/64, B*H), 128 threads = 4 warps; warp owns 16 q-rows x full 64-col
// j tile -> warp-local online softmax. Q frags live in REGISTERS.
#define FL_SMEM (53248)

__global__ __launch_bounds__(128, 4)
void flash_tf32(const float* __restrict__ q, const float* __restrict__ k,
                const float* __restrict__ v,
                const __nv_bfloat16* __restrict__ biash,
                float* __restrict__ o)
{
    extern __shared__ char smem_raw[];
    float* Ks = (float*)smem_raw;                 // [64][68]
    float* Vs = Ks + 64*68;                       // [64][72]
    float* Ps = Vs + 64*72;                       // [64][68] swizzled (union w/ bias)
    __nv_bfloat16* Bb = (__nv_bfloat16*)Ps;       // bias: warp w rows at w*2176 + (r&15)*72

    const int z = blockIdx.y;
    const int b = z >> 3, h = z & 7;
    const int i0 = blockIdx.x * 64;
    const float* qp = q + (size_t)b*T_*D_ + h*HD_;
    const float* kp = k + (size_t)b*T_*D_ + h*HD_;
    const float* vp = v + (size_t)b*T_*D_ + h*HD_;
    const __nv_bfloat16* bp = biash + (size_t)z*T_*T_;

    const int tid = threadIdx.x;
    const int warp = tid >> 5, lane = tid & 31;
    const int g = lane >> 2, qd = lane & 3;
    const int slab = warp * 16;
    const int sw = (g & 3) << 3;          // swizzle for rows slab+g, slab+g+8
    float* Pw = Ps + warp * 1088;         // this warp's P slab [16][68]

    // stage Q through Ps once, lift this warp's frags into registers
    #pragma unroll
    for (int u = 0; u < 8; u++) {
        const int idx = u*128 + tid;
        const int r = idx >> 4, d4 = idx & 15;
        float4 val = cvt4(*(const float4*)&qp[(size_t)(i0 + r)*D_ + d4*4]);
        *(float4*)&Ps[r*68 + ((d4*4) ^ ((r & 3) << 3))] = val;
    }
    __syncthreads();
    float qf[8][4];
    #pragma unroll
    for (int kk = 0; kk < 8; kk++) {
        const int kb = kk * 8;
        const int mr = slab + g;
        qf[kk][0] = Ps[ mr     *68 + ((kb + qd    ) ^ sw)];
        qf[kk][1] = Ps[(mr + 8)*68 + ((kb + qd    ) ^ sw)];
        qf[kk][2] = Ps[ mr     *68 + ((kb + qd + 4) ^ sw)];
        qf[kk][3] = Ps[(mr + 8)*68 + ((kb + qd + 4) ^ sw)];
    }
    // first loop iteration begins with __syncthreads -> safe to reuse Ps

    float m0 = -1e30f, m1 = -1e30f, l0 = 0.f, l1 = 0.f;
    float oacc[8][4];
    #pragma unroll
    for (int n = 0; n < 8; n++)
        #pragma unroll
        for (int u = 0; u < 4; u++) oacc[n][u] = 0.f;

    for (int jt = 0; jt < T_/64; jt++) {
        const int j0 = jt * 64;
        __syncthreads();   // prev iter's PV done with Vs/Ps; safe to overwrite
        #pragma unroll
        for (int u = 0; u < 8; u++) {
            const int idx = u*128 + tid;
            const int r = idx >> 4, d4 = idx & 15;
            *(float4*)&Ks[r*68 + d4*4] = cvt4(*(const float4*)&kp[(size_t)(j0 + r)*D_ + d4*4]);
            *(float4*)&Vs[r*72 + d4*4] = cvt4(*(const float4*)&vp[(size_t)(j0 + r)*D_ + d4*4]);
        }
        #pragma unroll
        for (int u = 0; u < 4; u++) {      // bias: 64 rows x 8 uint4
            const int idx = u*128 + tid;
            const int br = idx >> 3, seg = idx & 7;
            *(uint4*)&Bb[(br >> 4)*2176 + (br & 15)*72 + seg*8] =
                *(const uint4*)&bp[(size_t)(i0 + br)*T_ + j0 + seg*8];
        }
        __syncthreads();

        // S = Q K^T (Q frags from registers)
        float sacc[8][4];
        #pragma unroll
        for (int n = 0; n < 8; n++)
            #pragma unroll
            for (int u = 0; u < 4; u++) sacc[n][u] = 0.f;
        #pragma unroll
        for (int kk = 0; kk < 8; kk++) {
            const int kb = kk * 8;
            #pragma unroll
            for (int n = 0; n < 8; n++) {
                const int nr = n*8 + g;
                float bfr[2];
                bfr[0] = Ks[nr*68 + kb + qd];
                bfr[1] = Ks[nr*68 + kb + qd + 4];
                mma8(sacc[n], qf[kk], bfr);
            }
        }

        // epilogue: s2 = sacc*SC2 + bias2 (log2 domain), online softmax
        float sv[8][4];
        float mx0 = -1e30f, mx1 = -1e30f;
        #pragma unroll
        for (int n = 0; n < 8; n++) {
            const int c = n*8 + qd*2;
            const float2 bv0 = __bfloat1622float2(*(const __nv_bfloat162*)&Bb[warp*2176 + g    *72 + c]);
            const float2 bv1 = __bfloat1622float2(*(const __nv_bfloat162*)&Bb[warp*2176 + (g+8)*72 + c]);
            sv[n][0] = fmaf(sacc[n][0], SC2_, bv0.x);
            sv[n][1] = fmaf(sacc[n][1], SC2_, bv0.y);
            sv[n][2] = fmaf(sacc[n][2], SC2_, bv1.x);
            sv[n][3] = fmaf(sacc[n][3], SC2_, bv1.y);
            mx0 = fmaxf(mx0, fmaxf(sv[n][0], sv[n][1]));
            mx1 = fmaxf(mx1, fmaxf(sv[n][2], sv[n][3]));
        }
        mx0 = fmaxf(mx0, __shfl_xor_sync(0xffffffffu, mx0, 1));
        mx0 = fmaxf(mx0, __shfl_xor_sync(0xffffffffu, mx0, 2));
        mx1 = fmaxf(mx1, __shfl_xor_sync(0xffffffffu, mx1, 1));
        mx1 = fmaxf(mx1, __shfl_xor_sync(0xffffffffu, mx1, 2));

        __syncwarp();      // all bias-frag reads in this warp done before P writes

        const float mn0 = fmaxf(m0, mx0), mn1 = fmaxf(m1, mx1);
        const float al0 = ex2(m0 - mn0),  al1 = ex2(m1 - mn1);
        float rs0 = 0.f, rs1 = 0.f;
        #pragma unroll
        for (int n = 0; n < 8; n++) {
            const float p0 = ex2(sv[n][0] - mn0);
            const float p1 = ex2(sv[n][1] - mn0);
            const float p2 = ex2(sv[n][2] - mn1);
            const float p3 = ex2(sv[n][3] - mn1);
            rs0 += p0 + p1; rs1 += p2 + p3;
            const int c = (n*8 + qd*2) ^ sw;
            *(float2*)&Pw[ g    *68 + c] = make_float2(to_tf32(p0), to_tf32(p1));
            *(float2*)&Pw[(g+8)*68 + c] = make_float2(to_tf32(p2), to_tf32(p3));
            oacc[n][0] *= al0; oacc[n][1] *= al0;
            oacc[n][2] *= al1; oacc[n][3] *= al1;
        }
        rs0 += __shfl_xor_sync(0xffffffffu, rs0, 1);
        rs0 += __shfl_xor_sync(0xffffffffu, rs0, 2);
        rs1 += __shfl_xor_sync(0xffffffffu, rs1, 1);
        rs1 += __shfl_xor_sync(0xffffffffu, rs1, 2);
        l0 = l0*al0 + rs0;  m0 = mn0;
        l1 = l1*al1 + rs1;  m1 = mn1;

        __syncwarp();      // P rows warp-private; intra-warp visibility only

        // O += P @ V
        #pragma unroll
        for (int kk = 0; kk < 8; kk++) {
            const int kb = kk * 8;
            float afr[4];
            afr[0] = Pw[ g    *68 + ((kb + qd    ) ^ sw)];
            afr[1] = Pw[(g+8)*68 + ((kb + qd    ) ^ sw)];
            afr[2] = Pw[ g    *68 + ((kb + qd + 4) ^ sw)];
            afr[3] = Pw[(g+8)*68 + ((kb + qd + 4) ^ sw)];
            #pragma unroll
            for (int n = 0; n < 8; n++) {
                float bfr[2];
                bfr[0] = Vs[(kb + qd    )*72 + n*8 + g];
                bfr[1] = Vs[(kb + qd + 4)*72 + n*8 + g];
                mma8(oacc[n], afr, bfr);
            }
        }
    }

    const float inv0 = 1.0f / l0, inv1 = 1.0f / l1;
    const size_t r0 = (size_t)b*T_ + i0 + slab + g;
    #pragma unroll
    for (int n = 0; n < 8; n++) {
        const int c = h*HD_ + n*8 + qd*2;
        *(float2*)&o[ r0      * D_ + c] = make_float2(oacc[n][0]*inv0, oacc[n][1]*inv0);
        *(float2*)&o[(r0 + 8) * D_ + c] = make_float2(oacc[n][2]*inv1, oacc[n][3]*inv1);
    }
}

// ---------------- embedding extras ------------------------------------------
__global__ void add_cent_kernel(float* __restrict__ h, const float* __restrict__ cent,
                                const float* __restrict__ cw, const float* __restrict__ cb)
{
    const int n = blockIdx.x, d = threadIdx.x;
    h[(size_t)n * D_ + d] += cent[n] * cw[d] + cb[d];
}

// biash[b,h,i,j] = (edge_emb[et,h] + dist_emb[sp,h]) * log2(e)  as bf16
// vectorized: each thread handles 4 consecutive j -> int4 loads, 8B stores.
__global__ __launch_bounds__(256)
void bias_kernel(const int* __restrict__ et, const int* __restrict__ sp,
                 const float* __restrict__ ee, const float* __restrict__ de,
                 __nv_bfloat16* __restrict__ bias)
{
    const size_t t4   = (size_t)blockIdx.x * blockDim.x + threadIdx.x;  // B*T*T/4
    const size_t base = t4 * 4;
    const int4 e4 = *(const int4*)&et[base];
    int4 s4 = *(const int4*)&sp[base];
    s4.x = min(max(s4.x, 0), MD_); s4.y = min(max(s4.y, 0), MD_);
    s4.z = min(max(s4.z, 0), MD_); s4.w = min(max(s4.w, 0), MD_);
    const size_t j = base & (T_ - 1);
    const size_t i = (base >> 10) & (T_ - 1);
    const size_t b = base >> 20;
    #pragma unroll
    for (int hh = 0; hh < H_; hh++) {
        __nv_bfloat16 o0 = __float2bfloat16((ee[e4.x*H_ + hh] + de[s4.x*H_ + hh]) * LOG2E_);
        __nv_bfloat16 o1 = __float2bfloat16((ee[e4.y*H_ + hh] + de[s4.y*H_ + hh]) * LOG2E_);
        __nv_bfloat16 o2 = __float2bfloat16((ee[e4.z*H_ + hh] + de[s4.z*H_ + hh]) * LOG2E_);
        __nv_bfloat16 o3 = __float2bfloat16((ee[e4.w*H_ + hh] + de[s4.w*H_ + hh]) * LOG2E_);
        __nv_bfloat162 p01 = __halves2bfloat162(o0, o1);
        __nv_bfloat162 p23 = __halves2bfloat162(o2, o3);
        uint2 pk;
        pk.x = *(uint32_t*)&p01;
        pk.y = *(uint32_t*)&p23;
        *(uint2*)&bias[(((b*H_ + hh)*T_ + i)*T_) + j] = pk;
    }
}

// ---------------- layernorm --------------------------------------------------
__global__ __launch_bounds__(128)
void ln_kernel(const float* __restrict__ h, const float* __restrict__ w,
               const float* __restrict__ b, float* __restrict__ out)
{
    __shared__ float red[8];
    const int t = threadIdx.x;
    const float* hp = h + (size_t)blockIdx.x * D_;
    float v[4]; float s = 0.f, s2 = 0.f;
    #pragma unroll
    for (int u = 0; u < 4; u++) { v[u] = hp[t + u*128]; s += v[u]; s2 += v[u]*v[u]; }
    s  = warp_red_sum(s);
    s2 = warp_red_sum(s2);
    if ((t & 31) == 0) { red[t>>5] = s; red[4 + (t>>5)] = s2; }
    __syncthreads();
    s  = red[0] + red[1] + red[2] + red[3];
    s2 = red[4] + red[5] + red[6] + red[7];
    const float m   = s  * (1.0f / D_);
    const float var = s2 * (1.0f / D_) - m * m;
    const float r   = rsqrtf(var + 1e-5f);
    float* op = out + (size_t)blockIdx.x * D_;
    #pragma unroll
    for (int u = 0; u < 4; u++) {
        const int d = t + u*128;
        op[d] = (v[u] - m) * r * w[d] + b[d];
    }
}

// ---------------- host-side orchestration -----------------------------------
static inline void gemm1(const float* A, const float* W, const float* bias,
                         const float* resid, float* C, int K, int N, int act)
{
    GemmP p;
    p.A = A;
    p.W[0] = p.W[1] = p.W[2] = W;
    p.bias[0] = p.bias[1] = p.bias[2] = bias;
    p.C[0] = p.C[1] = p.C[2] = C;
    p.resid = resid;
    p.K = K; p.N = N;
    dim3 g(N / 128, NT_ / 128, 1);
    if (act == 1)        gemm_tf32<1,false><<<g,512,GEMM_SMEM>>>(p);
    else if (resid)      gemm_tf32<0,true ><<<g,512,GEMM_SMEM>>>(p);
    else                 gemm_tf32<0,false><<<g,512,GEMM_SMEM>>>(p);
}

extern "C" void kernel_launch(void* const* d_in, const int* in_sizes, int n_in,
                              void* d_out, int out_size)
{
    const float* nf     = (const float*)d_in[0];
    const float* cent   = (const float*)d_in[1];
    const int*   et     = (const int*)  d_in[2];
    const int*   sp     = (const int*)  d_in[3];
    const float* node_W = (const float*)d_in[4];
    const float* node_b = (const float*)d_in[5];
    const float* cent_W = (const float*)d_in[6];
    const float* cent_b = (const float*)d_in[7];
    const float* e_emb  = (const float*)d_in[8];
    const float* d_emb  = (const float*)d_in[9];
    const float* ln1w   = (const float*)d_in[10];
    const float* ln1b   = (const float*)d_in[11];
    const float* qW     = (const float*)d_in[12];
    const float* qb     = (const float*)d_in[13];
    const float* kW     = (const float*)d_in[14];
    const float* kb     = (const float*)d_in[15];
    const float* vW     = (const float*)d_in[16];
    const float* vb     = (const float*)d_in[17];
    const float* oW     = (const float*)d_in[18];
    const float* ob     = (const float*)d_in[19];
    const float* ln2w   = (const float*)d_in[20];
    const float* ln2b   = (const float*)d_in[21];
    const float* f1W    = (const float*)d_in[22];
    const float* f1b    = (const float*)d_in[23];
    const float* f2W    = (const float*)d_in[24];
    const float* f2b    = (const float*)d_in[25];

    float* h = (float*)d_out;

    float *px, *pq, *pk, *pv, *po, *pffn;
    __nv_bfloat16* pbias;
    cudaGetSymbolAddress((void**)&px,    g_x);
    cudaGetSymbolAddress((void**)&pq,    g_q);
    cudaGetSymbolAddress((void**)&pk,    g_k);
    cudaGetSymbolAddress((void**)&pv,    g_v);
    cudaGetSymbolAddress((void**)&po,    g_o);
    cudaGetSymbolAddress((void**)&pffn,  g_ffn);
    cudaGetSymbolAddress((void**)&pbias, g_biash);

    cudaFuncSetAttribute(flash_tf32, cudaFuncAttributeMaxDynamicSharedMemorySize, FL_SMEM);
    cudaFuncSetAttribute(gemm_tf32<0,false>, cudaFuncAttributeMaxDynamicSharedMemorySize, GEMM_SMEM);
    cudaFuncSetAttribute(gemm_tf32<0,true >, cudaFuncAttributeMaxDynamicSharedMemorySize, GEMM_SMEM);
    cudaFuncSetAttribute(gemm_tf32<1,false>, cudaFuncAttributeMaxDynamicSharedMemorySize, GEMM_SMEM);

    // embedding: h = nf @ node_W + node_b ; h += cent*cent_W + cent_b
    gemm1(nf, node_W, node_b, nullptr, h, F_, D_, 0);
    add_cent_kernel<<<NT_, D_>>>(h, cent, cent_W, cent_b);

    // Graphormer attention bias (layer-invariant), bf16, log2e pre-folded
    bias_kernel<<<(B_*T_*T_)/(256*4), 256>>>(et, sp, e_emb, d_emb, pbias);

    for (int l = 0; l < L_; l++) {
        const size_t wd = (size_t)l * D_ * D_;
        // x = LN1(h)
        ln_kernel<<<NT_, 128>>>(h, ln1w + l*D_, ln1b + l*D_, px);
        // q,k,v in one batched launch (grid.z = 3)
        {
            GemmP p;
            p.A = px;
            p.W[0] = qW + wd;  p.W[1] = kW + wd;  p.W[2] = vW + wd;
            p.bias[0] = qb + l*D_; p.bias[1] = kb + l*D_; p.bias[2] = vb + l*D_;
            p.C[0] = pq; p.C[1] = pk; p.C[2] = pv;
            p.resid = nullptr;
            p.K = D_; p.N = D_;
            gemm_tf32<0,false><<<dim3(D_/128, NT_/128, 3), 512, GEMM_SMEM>>>(p);
        }
        // fused attention: scores + softmax + AV, no global scores
        flash_tf32<<<dim3(T_/64, B_*H_), 128, FL_SMEM>>>(pq, pk, pv, pbias, po);
        // h += o @ oW + ob
        gemm1(po, oW + wd, ob + l*D_, h, h, D_, D_, 0);
        // FFN
        ln_kernel<<<NT_, 128>>>(h, ln2w + l*D_, ln2b + l*D_, px);
        gemm1(px,   f1W + (size_t)l*D_*DFF_, f1b + l*DFF_, nullptr, pffn, D_,   DFF_, 1);
        gemm1(pffn, f2W + (size_t)l*DFF_*D_, f2b + l*D_,   h,       h,    DFF_, D_,   0);
    }
}

// round 12
// speedup vs baseline: 1.3049x; 1.2762x over previous
#include <cuda_runtime.h>
#include <cuda_bf16.h>
#include <cuda_fp16.h>
#include <math.h>
#include <stdint.h>

#define B_ 4
#define T_ 1024
#define F_ 128
#define D_ 512
#define H_ 8
#define L_ 4
#define DFF_ 2048
#define MD_ 20
#define HD_ 64
#define NT_ (B_*T_)
#define SCALE_ 0.125f
#define LOG2E_ 1.4426950408889634f
#define SC2_ (SCALE_*LOG2E_)

// ---------------- scratch (device globals: no allocations allowed) ----------
__device__ float g_x  [NT_*(size_t)D_];
__device__ float g_q  [NT_*(size_t)D_];
__device__ float g_k  [NT_*(size_t)D_];
__device__ float g_v  [NT_*(size_t)D_];
__device__ float g_o  [NT_*(size_t)D_];
__device__ float g_ffn[NT_*(size_t)DFF_];
__device__ __nv_bfloat16 g_biash[(size_t)B_*H_*T_*T_];   // bias * log2(e), bf16
// transposed (K-major, [N][K]) fp16 weights: embed + 4 layers * (q,k,v,o,f1,f2)
#define WT_EMB_SZ   (F_*D_)                 // 65536
#define WT_L_STRIDE (4*D_*D_ + 2*D_*DFF_)   // 3145728
__device__ __half g_wt[WT_EMB_SZ + L_*(size_t)WT_L_STRIDE];   // ~25.3 MB

// ---------------- helpers ----------------------------------------------------
__device__ __forceinline__ float to_tf32(float x) {
    float y; asm("cvt.rna.tf32.f32 %0, %1;" : "=f"(y) : "f"(x)); return y;
}
__device__ __forceinline__ float4 cvt4(float4 v) {
    v.x = to_tf32(v.x); v.y = to_tf32(v.y); v.z = to_tf32(v.z); v.w = to_tf32(v.w);
    return v;
}
__device__ __forceinline__ float ex2(float x) {
    float y; asm("ex2.approx.f32 %0, %1;" : "=f"(y) : "f"(x)); return y;
}
__device__ __forceinline__ uint32_t pack_h2(float a, float b) {
    __half2 h = __floats2half2_rn(a, b);
    return *(uint32_t*)&h;
}
// tf32 mma (flash kernel, proven)
__device__ __forceinline__ void mma8(float* d, const float* a, const float* b) {
    asm volatile(
      "mma.sync.aligned.m16n8k8.row.col.f32.tf32.tf32.f32 "
      "{%0,%1,%2,%3}, {%4,%5,%6,%7}, {%8,%9}, {%0,%1,%2,%3};\n"
      : "+f"(d[0]), "+f"(d[1]), "+f"(d[2]), "+f"(d[3])
      : "r"(__float_as_uint(a[0])), "r"(__float_as_uint(a[1])),
        "r"(__float_as_uint(a[2])), "r"(__float_as_uint(a[3])),
        "r"(__float_as_uint(b[0])), "r"(__float_as_uint(b[1])));
}
// fp16 mma m16n8k16, fp32 accumulate (GEMM path): 2x MACs per instruction
__device__ __forceinline__ void mma16(float* d, const uint32_t* a, const uint32_t* b) {
    asm volatile(
      "mma.sync.aligned.m16n8k16.row.col.f32.f16.f16.f32 "
      "{%0,%1,%2,%3}, {%4,%5,%6,%7}, {%8,%9}, {%0,%1,%2,%3};\n"
      : "+f"(d[0]), "+f"(d[1]), "+f"(d[2]), "+f"(d[3])
      : "r"(a[0]), "r"(a[1]), "r"(a[2]), "r"(a[3]), "r"(b[0]), "r"(b[1]));
}
__device__ __forceinline__ float warp_red_sum(float v) {
    #pragma unroll
    for (int o = 16; o > 0; o >>= 1) v += __shfl_xor_sync(0xffffffffu, v, o);
    return v;
}

// ---------------- fp16 GEMM: C[4096, N] = act(A[4096,K] @ W + bias) (+resid) -
// W pre-transposed to fp16 [N][K]. 128x128x32 block tile, 512 threads,
// warp tile 32x32 (2x4 m16n8k16 frags). Smem layout: uint32 [row][20]
// (fp16x2 pairs, pad 20 -> frag reads row*20+qd(+4) are conflict-free).
// Two-stage double buffer, one __syncthreads per K-chunk.
#define HBUF 2560                       // uint32 per buffer (128*20)
#define GEMM_SMEM (4*HBUF*4)            // 40960 B

struct GemmP {
    const float* A;
    const __half* W[3];     // transposed [N][K] fp16
    const float* bias[3];
    float*       C[3];
    const float* resid;
    int K, N;
};

template<int ACT, bool RESID>
__global__ __launch_bounds__(512)
void gemm_fp16(GemmP p)
{
    extern __shared__ uint32_t sm32[];
    uint32_t* Asb = sm32;               // [2][128*20]
    uint32_t* Bsb = sm32 + 2*HBUF;      // [2][128*20]

    const int z = blockIdx.z;
    const float*  __restrict__ A     = p.A;
    const __half* __restrict__ W     = p.W[z];
    const float*  __restrict__ bias  = p.bias[z];
    float*        __restrict__ C     = p.C[z];
    const float*  __restrict__ resid = p.resid;
    const int K = p.K, N = p.N;
    const int m0 = blockIdx.y * 128, n0 = blockIdx.x * 128;

    const int tid  = threadIdx.x;
    const int warp = tid >> 5, lane = tid & 31;
    const int g  = lane >> 2, qd = lane & 3;
    const int wm = (warp >> 2) * 32;    // 0,32,64,96
    const int wn = (warp & 3)  * 32;    // 0,32,64,96

    // A loaders: 2 float4/thread (idx = tid+512i: row=idx>>3, seg=idx&7)
    // B loaders: 1 uint4/thread  (row=tid>>2, quad=tid&3 -> 8 halfs)
    const int a_r0 = tid >> 3,  a_sg = tid & 7;
    const int a_r1 = (tid + 512) >> 3;
    const int b_r  = tid >> 2,  b_qu = tid & 3;

    float4 ra[2]; uint4 rbv;
    float acc[2][4][4];
    #pragma unroll
    for (int i = 0; i < 2; i++)
        #pragma unroll
        for (int j = 0; j < 4; j++)
            #pragma unroll
            for (int u = 0; u < 4; u++) acc[i][j][u] = 0.f;

    const int nk = K >> 5;

    // prologue: chunk 0 -> regs -> smem buf 0
    ra[0] = *(const float4*)&A[(size_t)(m0 + a_r0) * K + a_sg*4];
    ra[1] = *(const float4*)&A[(size_t)(m0 + a_r1) * K + a_sg*4];
    rbv   = *(const uint4*)&W[(size_t)(n0 + b_r) * K + b_qu*8];
    {
        uint32_t* As = Asb; uint32_t* Bs = Bsb;
        *(uint2*)&As[a_r0*20 + a_sg*2] = make_uint2(pack_h2(ra[0].x, ra[0].y), pack_h2(ra[0].z, ra[0].w));
        *(uint2*)&As[a_r1*20 + a_sg*2] = make_uint2(pack_h2(ra[1].x, ra[1].y), pack_h2(ra[1].z, ra[1].w));
        *(uint4*)&Bs[b_r*20 + b_qu*4]  = rbv;
    }
    __syncthreads();

    // chunk 1 -> regs (in flight during first mma block)
    if (nk > 1) {
        ra[0] = *(const float4*)&A[(size_t)(m0 + a_r0) * K + 32 + a_sg*4];
        ra[1] = *(const float4*)&A[(size_t)(m0 + a_r1) * K + 32 + a_sg*4];
        rbv   = *(const uint4*)&W[(size_t)(n0 + b_r) * K + 32 + b_qu*8];
    }

    for (int kt = 0; kt < nk; kt++) {
        const uint32_t* As = Asb + (kt & 1) * HBUF;
        const uint32_t* Bs = Bsb + (kt & 1) * HBUF;

        #pragma unroll
        for (int s = 0; s < 2; s++) {          // two k16 steps per 32-chunk
            const int pb = s * 8;              // fp16-pair base
            uint32_t afr[2][4], bfr[4][2];
            #pragma unroll
            for (int mi = 0; mi < 2; mi++) {
                const int m_ = wm + mi*16 + g;
                afr[mi][0] = As[ m_     *20 + pb + qd];
                afr[mi][1] = As[(m_ + 8)*20 + pb + qd];
                afr[mi][2] = As[ m_     *20 + pb + qd + 4];
                afr[mi][3] = As[(m_ + 8)*20 + pb + qd + 4];
            }
            #pragma unroll
            for (int ni = 0; ni < 4; ni++) {
                const int n_ = wn + ni*8 + g;
                bfr[ni][0] = Bs[n_*20 + pb + qd];
                bfr[ni][1] = Bs[n_*20 + pb + qd + 4];
            }
            #pragma unroll
            for (int mi = 0; mi < 2; mi++)
                #pragma unroll
                for (int ni = 0; ni < 4; ni++)
                    mma16(acc[mi][ni], afr[mi], bfr[ni]);
        }

        if (kt + 1 < nk) {
            // stage chunk kt+1 (already in regs) into the other buffer
            uint32_t* Asw = Asb + ((kt + 1) & 1) * HBUF;
            uint32_t* Bsw = Bsb + ((kt + 1) & 1) * HBUF;
            *(uint2*)&Asw[a_r0*20 + a_sg*2] = make_uint2(pack_h2(ra[0].x, ra[0].y), pack_h2(ra[0].z, ra[0].w));
            *(uint2*)&Asw[a_r1*20 + a_sg*2] = make_uint2(pack_h2(ra[1].x, ra[1].y), pack_h2(ra[1].z, ra[1].w));
            *(uint4*)&Bsw[b_r*20 + b_qu*4]  = rbv;
            // issue LDG for chunk kt+2
            if (kt + 2 < nk) {
                const int k0 = (kt + 2) << 5;
                ra[0] = *(const float4*)&A[(size_t)(m0 + a_r0) * K + k0 + a_sg*4];
                ra[1] = *(const float4*)&A[(size_t)(m0 + a_r1) * K + k0 + a_sg*4];
                rbv   = *(const uint4*)&W[(size_t)(n0 + b_r) * K + k0 + b_qu*8];
            }
            __syncthreads();
        }
    }

    // epilogue (acc layout identical to m16n8k8 path)
    #pragma unroll
    for (int mi = 0; mi < 2; mi++) {
        const int r0 = m0 + wm + mi*16 + g;
        #pragma unroll
        for (int ni = 0; ni < 4; ni++) {
            const int c0 = n0 + wn + ni*8 + qd*2;
            const float2 bv = *(const float2*)&bias[c0];
            float v0 = acc[mi][ni][0] + bv.x;
            float v1 = acc[mi][ni][1] + bv.y;
            float v2 = acc[mi][ni][2] + bv.x;
            float v3 = acc[mi][ni][3] + bv.y;
            if (ACT == 1) {
                v0 = v0 / (1.0f + __expf(-v0));
                v1 = v1 / (1.0f + __expf(-v1));
                v2 = v2 / (1.0f + __expf(-v2));
                v3 = v3 / (1.0f + __expf(-v3));
            }
            if (RESID) {
                const float2 r1 = *(const float2*)&resid[(size_t)r0 * N + c0];
                const float2 r2 = *(const float2*)&resid[(size_t)(r0 + 8) * N + c0];
                v0 += r1.x; v1 += r1.y; v2 += r2.x; v3 += r2.y;
            }
            *(float2*)&C[(size_t)r0       * N + c0] = make_float2(v0, v1);
            *(float2*)&C[(size_t)(r0 + 8) * N + c0] = make_float2(v2, v3);
        }
    }
}

// ---------------- weight transpose: W[K][N] fp32 -> WT[N][K] fp16 ------------
struct TEnt { const float* src; __half* dst; int K; int N; int t0; };
struct TTab { TEnt e[25]; int n; };

__global__ __launch_bounds__(256)
void transpose_w(TTab tab)
{
    __shared__ float tile[32][33];
    const int t = blockIdx.x;
    int mi = 0;
    #pragma unroll 1
    while (mi + 1 < tab.n && t >= tab.e[mi+1].t0) mi++;
    const TEnt e = tab.e[mi];
    const int lt  = t - e.t0;
    const int ntn = e.N >> 5;
    const int k0 = (lt / ntn) * 32, n0 = (lt % ntn) * 32;
    const int tid = threadIdx.x;
    #pragma unroll
    for (int i = 0; i < 4; i++) {
        const int idx = tid + 256*i;
        const int r = idx >> 5, c = idx & 31;
        tile[r][c] = e.src[(size_t)(k0 + r)*e.N + n0 + c];
    }
    __syncthreads();
    #pragma unroll
    for (int i = 0; i < 4; i++) {
        const int idx = tid + 256*i;
        const int r = idx >> 5, c = idx & 31;
        e.dst[(size_t)(n0 + r)*e.K + k0 + c] = __float2half_rn(tile[c][r]);
    }
}

// ---------------- fused flash attention v2 (tf32) — unchanged (proven) -------
#define FL_SMEM (53248)

__global__ __launch_bounds__(128, 4)
void flash_tf32(const float* __restrict__ q, const float* __restrict__ k,
                const float* __restrict__ v,
                const __nv_bfloat16* __restrict__ biash,
                float* __restrict__ o)
{
    extern __shared__ char smem_raw[];
    float* Ks = (float*)smem_raw;                 // [64][68]
    float* Vs = Ks + 64*68;                       // [64][72]
    float* Ps = Vs + 64*72;                       // [64][68] swizzled (union w/ bias)
    __nv_bfloat16* Bb = (__nv_bfloat16*)Ps;

    const int z = blockIdx.y;
    const int b = z >> 3, h = z & 7;
    const int i0 = blockIdx.x * 64;
    const float* qp = q + (size_t)b*T_*D_ + h*HD_;
    const float* kp = k + (size_t)b*T_*D_ + h*HD_;
    const float* vp = v + (size_t)b*T_*D_ + h*HD_;
    const __nv_bfloat16* bp = biash + (size_t)z*T_*T_;

    const int tid = threadIdx.x;
    const int warp = tid >> 5, lane = tid & 31;
    const int g = lane >> 2, qd = lane & 3;
    const int slab = warp * 16;
    const int sw = (g & 3) << 3;
    float* Pw = Ps + warp * 1088;

    #pragma unroll
    for (int u = 0; u < 8; u++) {
        const int idx = u*128 + tid;
        const int r = idx >> 4, d4 = idx & 15;
        float4 val = cvt4(*(const float4*)&qp[(size_t)(i0 + r)*D_ + d4*4]);
        *(float4*)&Ps[r*68 + ((d4*4) ^ ((r & 3) << 3))] = val;
    }
    __syncthreads();
    float qf[8][4];
    #pragma unroll
    for (int kk = 0; kk < 8; kk++) {
        const int kb = kk * 8;
        const int mr = slab + g;
        qf[kk][0] = Ps[ mr     *68 + ((kb + qd    ) ^ sw)];
        qf[kk][1] = Ps[(mr + 8)*68 + ((kb + qd    ) ^ sw)];
        qf[kk][2] = Ps[ mr     *68 + ((kb + qd + 4) ^ sw)];
        qf[kk][3] = Ps[(mr + 8)*68 + ((kb + qd + 4) ^ sw)];
    }

    float m0 = -1e30f, m1 = -1e30f, l0 = 0.f, l1 = 0.f;
    float oacc[8][4];
    #pragma unroll
    for (int n = 0; n < 8; n++)
        #pragma unroll
        for (int u = 0; u < 4; u++) oacc[n][u] = 0.f;

    for (int jt = 0; jt < T_/64; jt++) {
        const int j0 = jt * 64;
        __syncthreads();
        #pragma unroll
        for (int u = 0; u < 8; u++) {
            const int idx = u*128 + tid;
            const int r = idx >> 4, d4 = idx & 15;
            *(float4*)&Ks[r*68 + d4*4] = cvt4(*(const float4*)&kp[(size_t)(j0 + r)*D_ + d4*4]);
            *(float4*)&Vs[r*72 + d4*4] = cvt4(*(const float4*)&vp[(size_t)(j0 + r)*D_ + d4*4]);
        }
        #pragma unroll
        for (int u = 0; u < 4; u++) {
            const int idx = u*128 + tid;
            const int br = idx >> 3, seg = idx & 7;
            *(uint4*)&Bb[(br >> 4)*2176 + (br & 15)*72 + seg*8] =
                *(const uint4*)&bp[(size_t)(i0 + br)*T_ + j0 + seg*8];
        }
        __syncthreads();

        float sacc[8][4];
        #pragma unroll
        for (int n = 0; n < 8; n++)
            #pragma unroll
            for (int u = 0; u < 4; u++) sacc[n][u] = 0.f;
        #pragma unroll
        for (int kk = 0; kk < 8; kk++) {
            const int kb = kk * 8;
            #pragma unroll
            for (int n = 0; n < 8; n++) {
                const int nr = n*8 + g;
                float bfr[2];
                bfr[0] = Ks[nr*68 + kb + qd];
                bfr[1] = Ks[nr*68 + kb + qd + 4];
                mma8(sacc[n], qf[kk], bfr);
            }
        }

        float sv[8][4];
        float mx0 = -1e30f, mx1 = -1e30f;
        #pragma unroll
        for (int n = 0; n < 8; n++) {
            const int c = n*8 + qd*2;
            const float2 bv0 = __bfloat1622float2(*(const __nv_bfloat162*)&Bb[warp*2176 + g    *72 + c]);
            const float2 bv1 = __bfloat1622float2(*(const __nv_bfloat162*)&Bb[warp*2176 + (g+8)*72 + c]);
            sv[n][0] = fmaf(sacc[n][0], SC2_, bv0.x);
            sv[n][1] = fmaf(sacc[n][1], SC2_, bv0.y);
            sv[n][2] = fmaf(sacc[n][2], SC2_, bv1.x);
            sv[n][3] = fmaf(sacc[n][3], SC2_, bv1.y);
            mx0 = fmaxf(mx0, fmaxf(sv[n][0], sv[n][1]));
            mx1 = fmaxf(mx1, fmaxf(sv[n][2], sv[n][3]));
        }
        mx0 = fmaxf(mx0, __shfl_xor_sync(0xffffffffu, mx0, 1));
        mx0 = fmaxf(mx0, __shfl_xor_sync(0xffffffffu, mx0, 2));
        mx1 = fmaxf(mx1, __shfl_xor_sync(0xffffffffu, mx1, 1));
        mx1 = fmaxf(mx1, __shfl_xor_sync(0xffffffffu, mx1, 2));

        __syncwarp();

        const float mn0 = fmaxf(m0, mx0), mn1 = fmaxf(m1, mx1);
        const float al0 = ex2(m0 - mn0),  al1 = ex2(m1 - mn1);
        float rs0 = 0.f, rs1 = 0.f;
        #pragma unroll
        for (int n = 0; n < 8; n++) {
            const float p0 = ex2(sv[n][0] - mn0);
            const float p1 = ex2(sv[n][1] - mn0);
            const float p2 = ex2(sv[n][2] - mn1);
            const float p3 = ex2(sv[n][3] - mn1);
            rs0 += p0 + p1; rs1 += p2 + p3;
            const int c = (n*8 + qd*2) ^ sw;
            *(float2*)&Pw[ g    *68 + c] = make_float2(to_tf32(p0), to_tf32(p1));
            *(float2*)&Pw[(g+8)*68 + c] = make_float2(to_tf32(p2), to_tf32(p3));
            oacc[n][0] *= al0; oacc[n][1] *= al0;
            oacc[n][2] *= al1; oacc[n][3] *= al1;
        }
        rs0 += __shfl_xor_sync(0xffffffffu, rs0, 1);
        rs0 += __shfl_xor_sync(0xffffffffu, rs0, 2);
        rs1 += __shfl_xor_sync(0xffffffffu, rs1, 1);
        rs1 += __shfl_xor_sync(0xffffffffu, rs1, 2);
        l0 = l0*al0 + rs0;  m0 = mn0;
        l1 = l1*al1 + rs1;  m1 = mn1;

        __syncwarp();

        #pragma unroll
        for (int kk = 0; kk < 8; kk++) {
            const int kb = kk * 8;
            float afr[4];
            afr[0] = Pw[ g    *68 + ((kb + qd    ) ^ sw)];
            afr[1] = Pw[(g+8)*68 + ((kb + qd    ) ^ sw)];
            afr[2] = Pw[ g    *68 + ((kb + qd + 4) ^ sw)];
            afr[3] = Pw[(g+8)*68 + ((kb + qd + 4) ^ sw)];
            #pragma unroll
            for (int n = 0; n < 8; n++) {
                float bfr[2];
                bfr[0] = Vs[(kb + qd    )*72 + n*8 + g];
                bfr[1] = Vs[(kb + qd + 4)*72 + n*8 + g];
                mma8(oacc[n], afr, bfr);
            }
        }
    }

    const float inv0 = 1.0f / l0, inv1 = 1.0f / l1;
    const size_t r0 = (size_t)b*T_ + i0 + slab + g;
    #pragma unroll
    for (int n = 0; n < 8; n++) {
        const int c = h*HD_ + n*8 + qd*2;
        *(float2*)&o[ r0      * D_ + c] = make_float2(oacc[n][0]*inv0, oacc[n][1]*inv0);
        *(float2*)&o[(r0 + 8) * D_ + c] = make_float2(oacc[n][2]*inv1, oacc[n][3]*inv1);
    }
}

// ---------------- embedding extras ------------------------------------------
__global__ void add_cent_kernel(float* __restrict__ h, const float* __restrict__ cent,
                                const float* __restrict__ cw, const float* __restrict__ cb)
{
    const int n = blockIdx.x, d = threadIdx.x;
    h[(size_t)n * D_ + d] += cent[n] * cw[d] + cb[d];
}

__global__ __launch_bounds__(256)
void bias_kernel(const int* __restrict__ et, const int* __restrict__ sp,
                 const float* __restrict__ ee, const float* __restrict__ de,
                 __nv_bfloat16* __restrict__ bias)
{
    const size_t t4   = (size_t)blockIdx.x * blockDim.x + threadIdx.x;  // B*T*T/4
    const size_t base = t4 * 4;
    const int4 e4 = *(const int4*)&et[base];
    int4 s4 = *(const int4*)&sp[base];
    s4.x = min(max(s4.x, 0), MD_); s4.y = min(max(s4.y, 0), MD_);
    s4.z = min(max(s4.z, 0), MD_); s4.w = min(max(s4.w, 0), MD_);
    const size_t j = base & (T_ - 1);
    const size_t i = (base >> 10) & (T_ - 1);
    const size_t b = base >> 20;
    #pragma unroll
    for (int hh = 0; hh < H_; hh++) {
        __nv_bfloat16 o0 = __float2bfloat16((ee[e4.x*H_ + hh] + de[s4.x*H_ + hh]) * LOG2E_);
        __nv_bfloat16 o1 = __float2bfloat16((ee[e4.y*H_ + hh] + de[s4.y*H_ + hh]) * LOG2E_);
        __nv_bfloat16 o2 = __float2bfloat16((ee[e4.z*H_ + hh] + de[s4.z*H_ + hh]) * LOG2E_);
        __nv_bfloat16 o3 = __float2bfloat16((ee[e4.w*H_ + hh] + de[s4.w*H_ + hh]) * LOG2E_);
        __nv_bfloat162 p01 = __halves2bfloat162(o0, o1);
        __nv_bfloat162 p23 = __halves2bfloat162(o2, o3);
        uint2 pk;
        pk.x = *(uint32_t*)&p01;
        pk.y = *(uint32_t*)&p23;
        *(uint2*)&bias[(((b*H_ + hh)*T_ + i)*T_) + j] = pk;
    }
}

// ---------------- layernorm --------------------------------------------------
__global__ __launch_bounds__(128)
void ln_kernel(const float* __restrict__ h, const float* __restrict__ w,
               const float* __restrict__ b, float* __restrict__ out)
{
    __shared__ float red[8];
    const int t = threadIdx.x;
    const float* hp = h + (size_t)blockIdx.x * D_;
    float v[4]; float s = 0.f, s2 = 0.f;
    #pragma unroll
    for (int u = 0; u < 4; u++) { v[u] = hp[t + u*128]; s += v[u]; s2 += v[u]*v[u]; }
    s  = warp_red_sum(s);
    s2 = warp_red_sum(s2);
    if ((t & 31) == 0) { red[t>>5] = s; red[4 + (t>>5)] = s2; }
    __syncthreads();
    s  = red[0] + red[1] + red[2] + red[3];
    s2 = red[4] + red[5] + red[6] + red[7];
    const float m   = s  * (1.0f / D_);
    const float var = s2 * (1.0f / D_) - m * m;
    const float r   = rsqrtf(var + 1e-5f);
    float* op = out + (size_t)blockIdx.x * D_;
    #pragma unroll
    for (int u = 0; u < 4; u++) {
        const int d = t + u*128;
        op[d] = (v[u] - m) * r * w[d] + b[d];
    }
}

// ---------------- host-side orchestration -----------------------------------
static inline void gemm1(const float* A, const __half* WT, const float* bias,
                         const float* resid, float* C, int K, int N, int act)
{
    GemmP p;
    p.A = A;
    p.W[0] = p.W[1] = p.W[2] = WT;
    p.bias[0] = p.bias[1] = p.bias[2] = bias;
    p.C[0] = p.C[1] = p.C[2] = C;
    p.resid = resid;
    p.K = K; p.N = N;
    dim3 g(N / 128, NT_ / 128, 1);
    if (act == 1)        gemm_fp16<1,false><<<g,512,GEMM_SMEM>>>(p);
    else if (resid)      gemm_fp16<0,true ><<<g,512,GEMM_SMEM>>>(p);
    else                 gemm_fp16<0,false><<<g,512,GEMM_SMEM>>>(p);
}

extern "C" void kernel_launch(void* const* d_in, const int* in_sizes, int n_in,
                              void* d_out, int out_size)
{
    const float* nf     = (const float*)d_in[0];
    const float* cent   = (const float*)d_in[1];
    const int*   et     = (const int*)  d_in[2];
    const int*   sp     = (const int*)  d_in[3];
    const float* node_W = (const float*)d_in[4];
    const float* node_b = (const float*)d_in[5];
    const float* cent_W = (const float*)d_in[6];
    const float* cent_b = (const float*)d_in[7];
    const float* e_emb  = (const float*)d_in[8];
    const float* d_emb  = (const float*)d_in[9];
    const float* ln1w   = (const float*)d_in[10];
    const float* ln1b   = (const float*)d_in[11];
    const float* qW     = (const float*)d_in[12];
    const float* qb     = (const float*)d_in[13];
    const float* kW     = (const float*)d_in[14];
    const float* kb     = (const float*)d_in[15];
    const float* vW     = (const float*)d_in[16];
    const float* vb     = (const float*)d_in[17];
    const float* oW     = (const float*)d_in[18];
    const float* ob     = (const float*)d_in[19];
    const float* ln2w   = (const float*)d_in[20];
    const float* ln2b   = (const float*)d_in[21];
    const float* f1W    = (const float*)d_in[22];
    const float* f1b    = (const float*)d_in[23];
    const float* f2W    = (const float*)d_in[24];
    const float* f2b    = (const float*)d_in[25];

    float* h = (float*)d_out;

    float *px, *pq, *pk, *pv, *po, *pffn;
    __half* pwt;
    __nv_bfloat16* pbias;
    cudaGetSymbolAddress((void**)&px,    g_x);
    cudaGetSymbolAddress((void**)&pq,    g_q);
    cudaGetSymbolAddress((void**)&pk,    g_k);
    cudaGetSymbolAddress((void**)&pv,    g_v);
    cudaGetSymbolAddress((void**)&po,    g_o);
    cudaGetSymbolAddress((void**)&pffn,  g_ffn);
    cudaGetSymbolAddress((void**)&pwt,   g_wt);
    cudaGetSymbolAddress((void**)&pbias, g_biash);

    cudaFuncSetAttribute(flash_tf32, cudaFuncAttributeMaxDynamicSharedMemorySize, FL_SMEM);

    // ---- transpose all weights into g_wt ([N][K] K-major, fp16) ----
    TTab tab;
    int te = 0, tiles = 0;
    auto addT = [&](const float* src, __half* dst, int K, int N) {
        tab.e[te].src = src; tab.e[te].dst = dst;
        tab.e[te].K = K; tab.e[te].N = N; tab.e[te].t0 = tiles;
        tiles += (K/32) * (N/32); te++;
    };
    addT(node_W, pwt, F_, D_);
    for (int l = 0; l < L_; l++) {
        __half* lb = pwt + WT_EMB_SZ + (size_t)l * WT_L_STRIDE;
        addT(qW + (size_t)l*D_*D_,   lb,                       D_,   D_);
        addT(kW + (size_t)l*D_*D_,   lb + D_*D_,               D_,   D_);
        addT(vW + (size_t)l*D_*D_,   lb + 2*D_*D_,             D_,   D_);
        addT(oW + (size_t)l*D_*D_,   lb + 3*D_*D_,             D_,   D_);
        addT(f1W + (size_t)l*D_*DFF_, lb + 4*D_*D_,            D_,   DFF_);
        addT(f2W + (size_t)l*DFF_*D_, lb + 4*D_*D_ + D_*DFF_,  DFF_, D_);
    }
    tab.n = te;
    transpose_w<<<tiles, 256>>>(tab);

    // embedding: h = nf @ node_W + node_b ; h += cent*cent_W + cent_b
    gemm1(nf, pwt, node_b, nullptr, h, F_, D_, 0);
    add_cent_kernel<<<NT_, D_>>>(h, cent, cent_W, cent_b);

    // Graphormer attention bias (layer-invariant), bf16, log2e pre-folded
    bias_kernel<<<(B_*T_*T_)/(256*4), 256>>>(et, sp, e_emb, d_emb, pbias);

    for (int l = 0; l < L_; l++) {
        __half* lb = pwt + WT_EMB_SZ + (size_t)l * WT_L_STRIDE;
        // x = LN1(h)
        ln_kernel<<<NT_, 128>>>(h, ln1w + l*D_, ln1b + l*D_, px);
        // q,k,v in one batched launch (grid.z = 3)
        {
            GemmP p;
            p.A = px;
            p.W[0] = lb;  p.W[1] = lb + D_*D_;  p.W[2] = lb + 2*D_*D_;
            p.bias[0] = qb + l*D_; p.bias[1] = kb + l*D_; p.bias[2] = vb + l*D_;
            p.C[0] = pq; p.C[1] = pk; p.C[2] = pv;
            p.resid = nullptr;
            p.K = D_; p.N = D_;
            gemm_fp16<0,false><<<dim3(D_/128, NT_/128, 3), 512, GEMM_SMEM>>>(p);
        }
        // fused attention: scores + softmax + AV, no global scores
        flash_tf32<<<dim3(T_/64, B_*H_), 128, FL_SMEM>>>(pq, pk, pv, pbias, po);
        // h += o @ oW + ob
        gemm1(po, lb + 3*D_*D_, ob + l*D_, h, h, D_, D_, 0);
        // FFN
        ln_kernel<<<NT_, 128>>>(h, ln2w + l*D_, ln2b + l*D_, px);
        gemm1(px,   lb + 4*D_*D_,            f1b + l*DFF_, nullptr, pffn, D_,   DFF_, 1);
        gemm1(pffn, lb + 4*D_*D_ + D_*DFF_,  f2b + l*D_,   h,       h,    DFF_, D_,   0);
    }
}

// round 14
// speedup vs baseline: 1.3566x; 1.0396x over previous
#include <cuda_runtime.h>
#include <cuda_bf16.h>
#include <cuda_fp16.h>
#include <math.h>
#include <stdint.h>

#define B_ 4
#define T_ 1024
#define F_ 128
#define D_ 512
#define H_ 8
#define L_ 4
#define DFF_ 2048
#define MD_ 20
#define HD_ 64
#define NT_ (B_*T_)
#define SCALE_ 0.125f
#define LOG2E_ 1.4426950408889634f
#define SC2_ (SCALE_*LOG2E_)

// ---------------- scratch (device globals: no allocations allowed) ----------
__device__ float g_x  [NT_*(size_t)D_];
__device__ float g_q  [NT_*(size_t)D_];
__device__ float g_k  [NT_*(size_t)D_];
__device__ float g_v  [NT_*(size_t)D_];
__device__ float g_o  [NT_*(size_t)D_];
__device__ float g_ffn[NT_*(size_t)DFF_];
__device__ __nv_bfloat16 g_biash[(size_t)B_*H_*T_*T_];   // bias * log2(e), bf16
// transposed (K-major, [N][K]) fp16 weights: embed + 4 layers * (q,k,v,o,f1,f2)
#define WT_EMB_SZ   (F_*D_)                 // 65536
#define WT_L_STRIDE (4*D_*D_ + 2*D_*DFF_)   // 3145728
__device__ __half g_wt[WT_EMB_SZ + L_*(size_t)WT_L_STRIDE];   // ~25.3 MB

// ---------------- helpers ----------------------------------------------------
__device__ __forceinline__ float ex2(float x) {
    float y; asm("ex2.approx.f32 %0, %1;" : "=f"(y) : "f"(x)); return y;
}
__device__ __forceinline__ uint32_t pack_h2(float a, float b) {
    __half2 h = __floats2half2_rn(a, b);
    return *(uint32_t*)&h;
}
// fp16 mma m16n8k16, fp32 accumulate
__device__ __forceinline__ void mma16(float* d, const uint32_t* a, const uint32_t* b) {
    asm volatile(
      "mma.sync.aligned.m16n8k16.row.col.f32.f16.f16.f32 "
      "{%0,%1,%2,%3}, {%4,%5,%6,%7}, {%8,%9}, {%0,%1,%2,%3};\n"
      : "+f"(d[0]), "+f"(d[1]), "+f"(d[2]), "+f"(d[3])
      : "r"(a[0]), "r"(a[1]), "r"(a[2]), "r"(a[3]), "r"(b[0]), "r"(b[1]));
}
__device__ __forceinline__ float warp_red_sum(float v) {
    #pragma unroll
    for (int o = 16; o > 0; o >>= 1) v += __shfl_xor_sync(0xffffffffu, v, o);
    return v;
}

// ---------------- fp16 GEMM (proven R12): 512 thr, 128x128x32, pad-20 -------
#define HBUF 2560                       // uint32 per buffer (128*20)
#define GEMM_SMEM (4*HBUF*4)            // 40960 B

struct GemmP {
    const float* A;
    const __half* W[3];     // transposed [N][K] fp16
    const float* bias[3];
    float*       C[3];
    const float* resid;
    int K, N;
};

template<int ACT, bool RESID>
__global__ __launch_bounds__(512)
void gemm_fp16(GemmP p)
{
    extern __shared__ uint32_t sm32[];
    uint32_t* Asb = sm32;               // [2][128*20]
    uint32_t* Bsb = sm32 + 2*HBUF;      // [2][128*20]

    const int z = blockIdx.z;
    const float*  __restrict__ A     = p.A;
    const __half* __restrict__ W     = p.W[z];
    const float*  __restrict__ bias  = p.bias[z];
    float*        __restrict__ C     = p.C[z];
    const float*  __restrict__ resid = p.resid;
    const int K = p.K, N = p.N;
    const int m0 = blockIdx.y * 128, n0 = blockIdx.x * 128;

    const int tid  = threadIdx.x;
    const int warp = tid >> 5, lane = tid & 31;
    const int g  = lane >> 2, qd = lane & 3;
    const int wm = (warp >> 2) * 32;
    const int wn = (warp & 3)  * 32;

    const int a_r0 = tid >> 3,  a_sg = tid & 7;
    const int a_r1 = (tid + 512) >> 3;
    const int b_r  = tid >> 2,  b_qu = tid & 3;

    float4 ra[2]; uint4 rbv;
    float acc[2][4][4];
    #pragma unroll
    for (int i = 0; i < 2; i++)
        #pragma unroll
        for (int j = 0; j < 4; j++)
            #pragma unroll
            for (int u = 0; u < 4; u++) acc[i][j][u] = 0.f;

    const int nk = K >> 5;

    ra[0] = *(const float4*)&A[(size_t)(m0 + a_r0) * K + a_sg*4];
    ra[1] = *(const float4*)&A[(size_t)(m0 + a_r1) * K + a_sg*4];
    rbv   = *(const uint4*)&W[(size_t)(n0 + b_r) * K + b_qu*8];
    {
        uint32_t* As = Asb; uint32_t* Bs = Bsb;
        *(uint2*)&As[a_r0*20 + a_sg*2] = make_uint2(pack_h2(ra[0].x, ra[0].y), pack_h2(ra[0].z, ra[0].w));
        *(uint2*)&As[a_r1*20 + a_sg*2] = make_uint2(pack_h2(ra[1].x, ra[1].y), pack_h2(ra[1].z, ra[1].w));
        *(uint4*)&Bs[b_r*20 + b_qu*4]  = rbv;
    }
    __syncthreads();

    if (nk > 1) {
        ra[0] = *(const float4*)&A[(size_t)(m0 + a_r0) * K + 32 + a_sg*4];
        ra[1] = *(const float4*)&A[(size_t)(m0 + a_r1) * K + 32 + a_sg*4];
        rbv   = *(const uint4*)&W[(size_t)(n0 + b_r) * K + 32 + b_qu*8];
    }

    for (int kt = 0; kt < nk; kt++) {
        const uint32_t* As = Asb + (kt & 1) * HBUF;
        const uint32_t* Bs = Bsb + (kt & 1) * HBUF;

        #pragma unroll
        for (int s = 0; s < 2; s++) {
            const int pb = s * 8;
            uint32_t afr[2][4], bfr[4][2];
            #pragma unroll
            for (int mi = 0; mi < 2; mi++) {
                const int m_ = wm + mi*16 + g;
                afr[mi][0] = As[ m_     *20 + pb + qd];
                afr[mi][1] = As[(m_ + 8)*20 + pb + qd];
                afr[mi][2] = As[ m_     *20 + pb + qd + 4];
                afr[mi][3] = As[(m_ + 8)*20 + pb + qd + 4];
            }
            #pragma unroll
            for (int ni = 0; ni < 4; ni++) {
                const int n_ = wn + ni*8 + g;
                bfr[ni][0] = Bs[n_*20 + pb + qd];
                bfr[ni][1] = Bs[n_*20 + pb + qd + 4];
            }
            #pragma unroll
            for (int mi = 0; mi < 2; mi++)
                #pragma unroll
                for (int ni = 0; ni < 4; ni++)
                    mma16(acc[mi][ni], afr[mi], bfr[ni]);
        }

        if (kt + 1 < nk) {
            uint32_t* Asw = Asb + ((kt + 1) & 1) * HBUF;
            uint32_t* Bsw = Bsb + ((kt + 1) & 1) * HBUF;
            *(uint2*)&Asw[a_r0*20 + a_sg*2] = make_uint2(pack_h2(ra[0].x, ra[0].y), pack_h2(ra[0].z, ra[0].w));
            *(uint2*)&Asw[a_r1*20 + a_sg*2] = make_uint2(pack_h2(ra[1].x, ra[1].y), pack_h2(ra[1].z, ra[1].w));
            *(uint4*)&Bsw[b_r*20 + b_qu*4]  = rbv;
            if (kt + 2 < nk) {
                const int k0 = (kt + 2) << 5;
                ra[0] = *(const float4*)&A[(size_t)(m0 + a_r0) * K + k0 + a_sg*4];
                ra[1] = *(const float4*)&A[(size_t)(m0 + a_r1) * K + k0 + a_sg*4];
                rbv   = *(const uint4*)&W[(size_t)(n0 + b_r) * K + k0 + b_qu*8];
            }
            __syncthreads();
        }
    }

    #pragma unroll
    for (int mi = 0; mi < 2; mi++) {
        const int r0 = m0 + wm + mi*16 + g;
        #pragma unroll
        for (int ni = 0; ni < 4; ni++) {
            const int c0 = n0 + wn + ni*8 + qd*2;
            const float2 bv = *(const float2*)&bias[c0];
            float v0 = acc[mi][ni][0] + bv.x;
            float v1 = acc[mi][ni][1] + bv.y;
            float v2 = acc[mi][ni][2] + bv.x;
            float v3 = acc[mi][ni][3] + bv.y;
            if (ACT == 1) {
                v0 = v0 / (1.0f + __expf(-v0));
                v1 = v1 / (1.0f + __expf(-v1));
                v2 = v2 / (1.0f + __expf(-v2));
                v3 = v3 / (1.0f + __expf(-v3));
            }
            if (RESID) {
                const float2 r1 = *(const float2*)&resid[(size_t)r0 * N + c0];
                const float2 r2 = *(const float2*)&resid[(size_t)(r0 + 8) * N + c0];
                v0 += r1.x; v1 += r1.y; v2 += r2.x; v3 += r2.y;
            }
            *(float2*)&C[(size_t)r0       * N + c0] = make_float2(v0, v1);
            *(float2*)&C[(size_t)(r0 + 8) * N + c0] = make_float2(v2, v3);
        }
    }
}

// ---------------- weight transpose: W[K][N] fp32 -> WT[N][K] fp16 ------------
struct TEnt { const float* src; __half* dst; int K; int N; int t0; };
struct TTab { TEnt e[25]; int n; };

__global__ __launch_bounds__(256)
void transpose_w(TTab tab)
{
    __shared__ float tile[32][33];
    const int t = blockIdx.x;
    int mi = 0;
    #pragma unroll 1
    while (mi + 1 < tab.n && t >= tab.e[mi+1].t0) mi++;
    const TEnt e = tab.e[mi];
    const int lt  = t - e.t0;
    const int ntn = e.N >> 5;
    const int k0 = (lt / ntn) * 32, n0 = (lt % ntn) * 32;
    const int tid = threadIdx.x;
    #pragma unroll
    for (int i = 0; i < 4; i++) {
        const int idx = tid + 256*i;
        const int r = idx >> 5, c = idx & 31;
        tile[r][c] = e.src[(size_t)(k0 + r)*e.N + n0 + c];
    }
    __syncthreads();
    #pragma unroll
    for (int i = 0; i < 4; i++) {
        const int idx = tid + 256*i;
        const int r = idx >> 5, c = idx & 31;
        e.dst[(size_t)(n0 + r)*e.K + k0 + c] = __float2half_rn(tile[c][r]);
    }
}

// ---------------- fused flash attention v3 (fp16 mma) ------------------------
// Grid (T/64, B*H), 128 threads = 4 warps; warp owns 16 q-rows x full 64-col
// j tile, warp-local online softmax. fp16 m16n8k16 for QK^T and PV.
// Smem (uint32 words, pad-36 rows -> conflict-free):
//   KsU [64][36]            Q staging then K tile (fp16 pairs along d)
//   VtU [64][36]            V TRANSPOSED: [d][j-pair] fp16 pairs along j
//   PwU [4 warps][16][36]   P tile fp16 pairs along j
//   Bb  bf16 [4 warps][16][72]  bias (stride 1152 bf16 per warp slab)
#define FLW_K  0
#define FLW_V  2304
#define FLW_P  4608
#define FLW_B  6912
#define FL_SMEM ((6912 + 2304)*4)   // 36864 B

__global__ __launch_bounds__(128, 4)
void flash_fp16(const float* __restrict__ q, const float* __restrict__ k,
                const float* __restrict__ v,
                const __nv_bfloat16* __restrict__ biash,
                float* __restrict__ o)
{
    extern __shared__ uint32_t smw[];
    uint32_t* KsU = smw + FLW_K;
    uint32_t* VtU = smw + FLW_V;
    __nv_bfloat16* Bb = (__nv_bfloat16*)(smw + FLW_B);

    const int z = blockIdx.y;
    const int b = z >> 3, h = z & 7;
    const int i0 = blockIdx.x * 64;
    const float* qp = q + (size_t)b*T_*D_ + h*HD_;
    const float* kp = k + (size_t)b*T_*D_ + h*HD_;
    const float* vp = v + (size_t)b*T_*D_ + h*HD_;
    const __nv_bfloat16* bp = biash + (size_t)z*T_*T_;

    const int tid = threadIdx.x;
    const int warp = tid >> 5, lane = tid & 31;
    const int g = lane >> 2, qd = lane & 3;
    const int slab = warp * 16;
    uint32_t* PwU = smw + FLW_P + warp * 576;    // [16][36]

    // stage Q (fp16 pairs) through KsU, lift this warp's frags into registers
    #pragma unroll
    for (int u = 0; u < 8; u++) {
        const int idx = u*128 + tid;
        const int r = idx >> 4, d4 = idx & 15;
        const float4 val = *(const float4*)&qp[(size_t)(i0 + r)*D_ + d4*4];
        *(uint2*)&KsU[r*36 + d4*2] = make_uint2(pack_h2(val.x, val.y), pack_h2(val.z, val.w));
    }
    __syncthreads();
    uint32_t qf[4][4];
    #pragma unroll
    for (int s = 0; s < 4; s++) {
        const int mr = slab + g;
        qf[s][0] = KsU[ mr     *36 + 8*s + qd];
        qf[s][1] = KsU[(mr + 8)*36 + 8*s + qd];
        qf[s][2] = KsU[ mr     *36 + 8*s + qd + 4];
        qf[s][3] = KsU[(mr + 8)*36 + 8*s + qd + 4];
    }
    // first loop iteration begins with __syncthreads -> safe to reuse KsU

    float m0 = -1e30f, m1 = -1e30f, l0 = 0.f, l1 = 0.f;
    float oacc[8][4];
    #pragma unroll
    for (int n = 0; n < 8; n++)
        #pragma unroll
        for (int u = 0; u < 4; u++) oacc[n][u] = 0.f;

    for (int jt = 0; jt < T_/64; jt++) {
        const int j0 = jt * 64;
        __syncthreads();   // prev iter's PV done with VtU/PwU; Q frags read
        // K tile: [j][d] fp16 pairs (d contiguous)
        #pragma unroll
        for (int u = 0; u < 8; u++) {
            const int idx = u*128 + tid;
            const int r = idx >> 4, d4 = idx & 15;
            const float4 val = *(const float4*)&kp[(size_t)(j0 + r)*D_ + d4*4];
            *(uint2*)&KsU[r*36 + d4*2] = make_uint2(pack_h2(val.x, val.y), pack_h2(val.z, val.w));
        }
        // V tile TRANSPOSED: VtU[d][jp] = (V[2jp][d], V[2jp+1][d])
        #pragma unroll
        for (int u = 0; u < 4; u++) {
            const int item = u*128 + tid;       // 512 items
            const int jp = item & 31, dg = item >> 5;
            const float4 vA = *(const float4*)&vp[(size_t)(j0 + 2*jp    )*D_ + dg*4];
            const float4 vB = *(const float4*)&vp[(size_t)(j0 + 2*jp + 1)*D_ + dg*4];
            VtU[(dg*4+0)*36 + jp] = pack_h2(vA.x, vB.x);
            VtU[(dg*4+1)*36 + jp] = pack_h2(vA.y, vB.y);
            VtU[(dg*4+2)*36 + jp] = pack_h2(vA.z, vB.z);
            VtU[(dg*4+3)*36 + jp] = pack_h2(vA.w, vB.w);
        }
        // bias: 64 rows x 8 uint4, warp-slab stride 1152 bf16 (16 rows x 72)
        #pragma unroll
        for (int u = 0; u < 4; u++) {
            const int idx = u*128 + tid;
            const int br = idx >> 3, seg = idx & 7;
            *(uint4*)&Bb[(br >> 4)*1152 + (br & 15)*72 + seg*8] =
                *(const uint4*)&bp[(size_t)(i0 + br)*T_ + j0 + seg*8];
        }
        __syncthreads();

        // S = Q K^T  (fp16 k16: 4 steps x 8 n-blocks)
        float sacc[8][4];
        #pragma unroll
        for (int n = 0; n < 8; n++)
            #pragma unroll
            for (int u = 0; u < 4; u++) sacc[n][u] = 0.f;
        #pragma unroll
        for (int s = 0; s < 4; s++) {
            #pragma unroll
            for (int n = 0; n < 8; n++) {
                const int nr = n*8 + g;
                uint32_t bfr[2];
                bfr[0] = KsU[nr*36 + 8*s + qd];
                bfr[1] = KsU[nr*36 + 8*s + qd + 4];
                mma16(sacc[n], qf[s], bfr);
            }
        }

        // online softmax (log2 domain), warp-local
        float sv[8][4];
        float mx0 = -1e30f, mx1 = -1e30f;
        #pragma unroll
        for (int n = 0; n < 8; n++) {
            const int c = n*8 + qd*2;
            const float2 bv0 = __bfloat1622float2(*(const __nv_bfloat162*)&Bb[warp*1152 + g    *72 + c]);
            const float2 bv1 = __bfloat1622float2(*(const __nv_bfloat162*)&Bb[warp*1152 + (g+8)*72 + c]);
            sv[n][0] = fmaf(sacc[n][0], SC2_, bv0.x);
            sv[n][1] = fmaf(sacc[n][1], SC2_, bv0.y);
            sv[n][2] = fmaf(sacc[n][2], SC2_, bv1.x);
            sv[n][3] = fmaf(sacc[n][3], SC2_, bv1.y);
            mx0 = fmaxf(mx0, fmaxf(sv[n][0], sv[n][1]));
            mx1 = fmaxf(mx1, fmaxf(sv[n][2], sv[n][3]));
        }
        mx0 = fmaxf(mx0, __shfl_xor_sync(0xffffffffu, mx0, 1));
        mx0 = fmaxf(mx0, __shfl_xor_sync(0xffffffffu, mx0, 2));
        mx1 = fmaxf(mx1, __shfl_xor_sync(0xffffffffu, mx1, 1));
        mx1 = fmaxf(mx1, __shfl_xor_sync(0xffffffffu, mx1, 2));

        const float mn0 = fmaxf(m0, mx0), mn1 = fmaxf(m1, mx1);
        const float al0 = ex2(m0 - mn0),  al1 = ex2(m1 - mn1);
        float rs0 = 0.f, rs1 = 0.f;
        #pragma unroll
        for (int n = 0; n < 8; n++) {
            const float p0 = ex2(sv[n][0] - mn0);
            const float p1 = ex2(sv[n][1] - mn0);
            const float p2 = ex2(sv[n][2] - mn1);
            const float p3 = ex2(sv[n][3] - mn1);
            rs0 += p0 + p1; rs1 += p2 + p3;
            PwU[ g    *36 + n*4 + qd] = pack_h2(p0, p1);
            PwU[(g+8)*36 + n*4 + qd] = pack_h2(p2, p3);
            oacc[n][0] *= al0; oacc[n][1] *= al0;
            oacc[n][2] *= al1; oacc[n][3] *= al1;
        }
        rs0 += __shfl_xor_sync(0xffffffffu, rs0, 1);
        rs0 += __shfl_xor_sync(0xffffffffu, rs0, 2);
        rs1 += __shfl_xor_sync(0xffffffffu, rs1, 1);
        rs1 += __shfl_xor_sync(0xffffffffu, rs1, 2);
        l0 = l0*al0 + rs0;  m0 = mn0;
        l1 = l1*al1 + rs1;  m1 = mn1;

        __syncwarp();      // P rows warp-private; intra-warp visibility only

        // O += P @ V   (A = P [16][j], B = Vt [d][j])
        #pragma unroll
        for (int s = 0; s < 4; s++) {
            uint32_t afr[4];
            afr[0] = PwU[ g    *36 + 8*s + qd];
            afr[1] = PwU[(g+8)*36 + 8*s + qd];
            afr[2] = PwU[ g    *36 + 8*s + qd + 4];
            afr[3] = PwU[(g+8)*36 + 8*s + qd + 4];
            #pragma unroll
            for (int n = 0; n < 8; n++) {
                const int nr = n*8 + g;
                uint32_t bfr[2];
                bfr[0] = VtU[nr*36 + 8*s + qd];
                bfr[1] = VtU[nr*36 + 8*s + qd + 4];
                mma16(oacc[n], afr, bfr);
            }
        }
    }

    const float inv0 = 1.0f / l0, inv1 = 1.0f / l1;
    const size_t r0 = (size_t)b*T_ + i0 + slab + g;
    #pragma unroll
    for (int n = 0; n < 8; n++) {
        const int c = h*HD_ + n*8 + qd*2;
        *(float2*)&o[ r0      * D_ + c] = make_float2(oacc[n][0]*inv0, oacc[n][1]*inv0);
        *(float2*)&o[(r0 + 8) * D_ + c] = make_float2(oacc[n][2]*inv1, oacc[n][3]*inv1);
    }
}

// ---------------- embedding extras ------------------------------------------
__global__ void add_cent_kernel(float* __restrict__ h, const float* __restrict__ cent,
                                const float* __restrict__ cw, const float* __restrict__ cb)
{
    const int n = blockIdx.x, d = threadIdx.x;
    h[(size_t)n * D_ + d] += cent[n] * cw[d] + cb[d];
}

// biash = (edge_emb[et] + dist_emb[sp]) * log2(e) as bf16, via smem LUT.
__global__ __launch_bounds__(256)
void bias_kernel(const int* __restrict__ et, const int* __restrict__ sp,
                 const float* __restrict__ ee, const float* __restrict__ de,
                 __nv_bfloat16* __restrict__ bias)
{
    __shared__ uint4 lut[336];
    const int tid = threadIdx.x;
    for (int i = tid; i < 336; i += 256) {
        const int e = i / 21, s = i % 21;
        uint32_t w[4];
        #pragma unroll
        for (int p = 0; p < 4; p++) {
            __nv_bfloat16 lo = __float2bfloat16((ee[e*H_ + 2*p    ] + de[s*H_ + 2*p    ]) * LOG2E_);
            __nv_bfloat16 hi = __float2bfloat16((ee[e*H_ + 2*p + 1] + de[s*H_ + 2*p + 1]) * LOG2E_);
            __nv_bfloat162 pr = __halves2bfloat162(lo, hi);
            w[p] = *(uint32_t*)&pr;
        }
        lut[i] = make_uint4(w[0], w[1], w[2], w[3]);
    }
    __syncthreads();

    const size_t t4   = (size_t)blockIdx.x * blockDim.x + tid;  // B*T*T/4
    const size_t base = t4 * 4;
    const int4 e4 = *(const int4*)&et[base];
    int4 s4 = *(const int4*)&sp[base];
    s4.x = min(max(s4.x, 0), MD_); s4.y = min(max(s4.y, 0), MD_);
    s4.z = min(max(s4.z, 0), MD_); s4.w = min(max(s4.w, 0), MD_);
    const uint4 L0 = lut[e4.x*21 + s4.x];
    const uint4 L1 = lut[e4.y*21 + s4.y];
    const uint4 L2 = lut[e4.z*21 + s4.z];
    const uint4 L3 = lut[e4.w*21 + s4.w];
    const uint32_t* lw[4] = { (const uint32_t*)&L0, (const uint32_t*)&L1,
                              (const uint32_t*)&L2, (const uint32_t*)&L3 };
    const size_t j = base & (T_ - 1);
    const size_t i = (base >> 10) & (T_ - 1);
    const size_t b = base >> 20;
    #pragma unroll
    for (int hh = 0; hh < H_; hh++) {
        const int wi = hh >> 1, sh = (hh & 1) * 16;
        const uint32_t h0 = (lw[0][wi] >> sh) & 0xffffu;
        const uint32_t h1 = (lw[1][wi] >> sh) & 0xffffu;
        const uint32_t h2 = (lw[2][wi] >> sh) & 0xffffu;
        const uint32_t h3 = (lw[3][wi] >> sh) & 0xffffu;
        uint2 pk;
        pk.x = h0 | (h1 << 16);
        pk.y = h2 | (h3 << 16);
        *(uint2*)&bias[(((b*H_ + hh)*T_ + i)*T_) + j] = pk;
    }
}

// ---------------- layernorm --------------------------------------------------
__global__ __launch_bounds__(128)
void ln_kernel(const float* __restrict__ h, const float* __restrict__ w,
               const float* __restrict__ b, float* __restrict__ out)
{
    __shared__ float red[8];
    const int t = threadIdx.x;
    const float* hp = h + (size_t)blockIdx.x * D_;
    float v[4]; float s = 0.f, s2 = 0.f;
    #pragma unroll
    for (int u = 0; u < 4; u++) { v[u] = hp[t + u*128]; s += v[u]; s2 += v[u]*v[u]; }
    s  = warp_red_sum(s);
    s2 = warp_red_sum(s2);
    if ((t & 31) == 0) { red[t>>5] = s; red[4 + (t>>5)] = s2; }
    __syncthreads();
    s  = red[0] + red[1] + red[2] + red[3];
    s2 = red[4] + red[5] + red[6] + red[7];
    const float m   = s  * (1.0f / D_);
    const float var = s2 * (1.0f / D_) - m * m;
    const float r   = rsqrtf(var + 1e-5f);
    float* op = out + (size_t)blockIdx.x * D_;
    #pragma unroll
    for (int u = 0; u < 4; u++) {
        const int d = t + u*128;
        op[d] = (v[u] - m) * r * w[d] + b[d];
    }
}

// ---------------- host-side orchestration -----------------------------------
static inline void gemm1(const float* A, const __half* WT, const float* bias,
                         const float* resid, float* C, int K, int N, int act)
{
    GemmP p;
    p.A = A;
    p.W[0] = p.W[1] = p.W[2] = WT;
    p.bias[0] = p.bias[1] = p.bias[2] = bias;
    p.C[0] = p.C[1] = p.C[2] = C;
    p.resid = resid;
    p.K = K; p.N = N;
    dim3 g(N / 128, NT_ / 128, 1);
    if (act == 1)        gemm_fp16<1,false><<<g,512,GEMM_SMEM>>>(p);
    else if (resid)      gemm_fp16<0,true ><<<g,512,GEMM_SMEM>>>(p);
    else                 gemm_fp16<0,false><<<g,512,GEMM_SMEM>>>(p);
}

extern "C" void kernel_launch(void* const* d_in, const int* in_sizes, int n_in,
                              void* d_out, int out_size)
{
    const float* nf     = (const float*)d_in[0];
    const float* cent   = (const float*)d_in[1];
    const int*   et     = (const int*)  d_in[2];
    const int*   sp     = (const int*)  d_in[3];
    const float* node_W = (const float*)d_in[4];
    const float* node_b = (const float*)d_in[5];
    const float* cent_W = (const float*)d_in[6];
    const float* cent_b = (const float*)d_in[7];
    const float* e_emb  = (const float*)d_in[8];
    const float* d_emb  = (const float*)d_in[9];
    const float* ln1w   = (const float*)d_in[10];
    const float* ln1b   = (const float*)d_in[11];
    const float* qW     = (const float*)d_in[12];
    const float* qb     = (const float*)d_in[13];
    const float* kW     = (const float*)d_in[14];
    const float* kb     = (const float*)d_in[15];
    const float* vW     = (const float*)d_in[16];
    const float* vb     = (const float*)d_in[17];
    const float* oW     = (const float*)d_in[18];
    const float* ob     = (const float*)d_in[19];
    const float* ln2w   = (const float*)d_in[20];
    const float* ln2b   = (const float*)d_in[21];
    const float* f1W    = (const float*)d_in[22];
    const float* f1b    = (const float*)d_in[23];
    const float* f2W    = (const float*)d_in[24];
    const float* f2b    = (const float*)d_in[25];

    float* h = (float*)d_out;

    float *px, *pq, *pk, *pv, *po, *pffn;
    __half* pwt;
    __nv_bfloat16* pbias;
    cudaGetSymbolAddress((void**)&px,    g_x);
    cudaGetSymbolAddress((void**)&pq,    g_q);
    cudaGetSymbolAddress((void**)&pk,    g_k);
    cudaGetSymbolAddress((void**)&pv,    g_v);
    cudaGetSymbolAddress((void**)&po,    g_o);
    cudaGetSymbolAddress((void**)&pffn,  g_ffn);
    cudaGetSymbolAddress((void**)&pwt,   g_wt);
    cudaGetSymbolAddress((void**)&pbias, g_biash);

    cudaFuncSetAttribute(flash_fp16, cudaFuncAttributeMaxDynamicSharedMemorySize, FL_SMEM);

    // ---- transpose all weights into g_wt ([N][K] K-major, fp16) ----
    TTab tab;
    int te = 0, tiles = 0;
    auto addT = [&](const float* src, __half* dst, int K, int N) {
        tab.e[te].src = src; tab.e[te].dst = dst;
        tab.e[te].K = K; tab.e[te].N = N; tab.e[te].t0 = tiles;
        tiles += (K/32) * (N/32); te++;
    };
    addT(node_W, pwt, F_, D_);
    for (int l = 0; l < L_; l++) {
        __half* lb = pwt + WT_EMB_SZ + (size_t)l * WT_L_STRIDE;
        addT(qW + (size_t)l*D_*D_,   lb,                       D_,   D_);
        addT(kW + (size_t)l*D_*D_,   lb + D_*D_,               D_,   D_);
        addT(vW + (size_t)l*D_*D_,   lb + 2*D_*D_,             D_,   D_);
        addT(oW + (size_t)l*D_*D_,   lb + 3*D_*D_,             D_,   D_);
        addT(f1W + (size_t)l*D_*DFF_, lb + 4*D_*D_,            D_,   DFF_);
        addT(f2W + (size_t)l*DFF_*D_, lb + 4*D_*D_ + D_*DFF_,  DFF_, D_);
    }
    tab.n = te;
    transpose_w<<<tiles, 256>>>(tab);

    // embedding: h = nf @ node_W + node_b ; h += cent*cent_W + cent_b
    gemm1(nf, pwt, node_b, nullptr, h, F_, D_, 0);
    add_cent_kernel<<<NT_, D_>>>(h, cent, cent_W, cent_b);

    // Graphormer attention bias (layer-invariant), bf16, log2e pre-folded
    bias_kernel<<<(B_*T_*T_)/(256*4), 256>>>(et, sp, e_emb, d_emb, pbias);

    for (int l = 0; l < L_; l++) {
        __half* lb = pwt + WT_EMB_SZ + (size_t)l * WT_L_STRIDE;
        // x = LN1(h)
        ln_kernel<<<NT_, 128>>>(h, ln1w + l*D_, ln1b + l*D_, px);
        // q,k,v in one batched launch (grid.z = 3)
        {
            GemmP p;
            p.A = px;
            p.W[0] = lb;  p.W[1] = lb + D_*D_;  p.W[2] = lb + 2*D_*D_;
            p.bias[0] = qb + l*D_; p.bias[1] = kb + l*D_; p.bias[2] = vb + l*D_;
            p.C[0] = pq; p.C[1] = pk; p.C[2] = pv;
            p.resid = nullptr;
            p.K = D_; p.N = D_;
            gemm_fp16<0,false><<<dim3(D_/128, NT_/128, 3), 512, GEMM_SMEM>>>(p);
        }
        // fused attention: scores + softmax + AV, no global scores
        flash_fp16<<<dim3(T_/64, B_*H_), 128, FL_SMEM>>>(pq, pk, pv, pbias, po);
        // h += o @ oW + ob
        gemm1(po, lb + 3*D_*D_, ob + l*D_, h, h, D_, D_, 0);
        // FFN
        ln_kernel<<<NT_, 128>>>(h, ln2w + l*D_, ln2b + l*D_, px);
        gemm1(px,   lb + 4*D_*D_,            f1b + l*DFF_, nullptr, pffn, D_,   DFF_, 1);
        gemm1(pffn, lb + 4*D_*D_ + D_*DFF_,  f2b + l*D_,   h,       h,    DFF_, D_,   0);
    }
}

// round 15
// speedup vs baseline: 1.3919x; 1.0260x over previous
#include <cuda_runtime.h>
#include <cuda_bf16.h>
#include <cuda_fp16.h>
#include <math.h>
#include <stdint.h>

#define B_ 4
#define T_ 1024
#define F_ 128
#define D_ 512
#define H_ 8
#define L_ 4
#define DFF_ 2048
#define MD_ 20
#define HD_ 64
#define NT_ (B_*T_)
#define SCALE_ 0.125f
#define LOG2E_ 1.4426950408889634f
#define SC2_ (SCALE_*LOG2E_)

// ---------------- scratch (device globals: no allocations allowed) ----------
__device__ __half g_x  [NT_*(size_t)D_];
__device__ __half g_q  [NT_*(size_t)D_];
__device__ __half g_k  [NT_*(size_t)D_];
__device__ __half g_v  [NT_*(size_t)D_];
__device__ __half g_o  [NT_*(size_t)D_];
__device__ __half g_ffn[NT_*(size_t)DFF_];
__device__ __nv_bfloat16 g_biash[(size_t)B_*H_*T_*T_];   // bias * log2(e), bf16
// transposed (K-major, [N][K]) fp16 weights: embed + 4 layers * (q,k,v,o,f1,f2)
#define WT_EMB_SZ   (F_*D_)                 // 65536
#define WT_L_STRIDE (4*D_*D_ + 2*D_*DFF_)   // 3145728
__device__ __half g_wt[WT_EMB_SZ + L_*(size_t)WT_L_STRIDE];   // ~25.3 MB

// ---------------- helpers ----------------------------------------------------
__device__ __forceinline__ float ex2(float x) {
    float y; asm("ex2.approx.f32 %0, %1;" : "=f"(y) : "f"(x)); return y;
}
__device__ __forceinline__ uint32_t pack_h2(float a, float b) {
    __half2 h = __floats2half2_rn(a, b);
    return *(uint32_t*)&h;
}
// fp16 mma m16n8k16, fp32 accumulate
__device__ __forceinline__ void mma16(float* d, const uint32_t* a, const uint32_t* b) {
    asm volatile(
      "mma.sync.aligned.m16n8k16.row.col.f32.f16.f16.f32 "
      "{%0,%1,%2,%3}, {%4,%5,%6,%7}, {%8,%9}, {%0,%1,%2,%3};\n"
      : "+f"(d[0]), "+f"(d[1]), "+f"(d[2]), "+f"(d[3])
      : "r"(a[0]), "r"(a[1]), "r"(a[2]), "r"(a[3]), "r"(b[0]), "r"(b[1]));
}
__device__ __forceinline__ float warp_red_sum(float v) {
    #pragma unroll
    for (int o = 16; o > 0; o >>= 1) v += __shfl_xor_sync(0xffffffffu, v, o);
    return v;
}

// ---------------- fp16 GEMM v4: fp16 A, fp16 W, optional fp16 C --------------
// C[4096, N] = act(A[4096,K] @ W + bias) (+resid). A fp16 [M][K],
// W pre-transposed fp16 [N][K]. 128x128x32 tile, 512 threads, 32x32 warp tile.
// Smem: uint32 [row][20] (fp16 pairs, pad 20 -> conflict-free frag reads).
// Two-stage double buffer, one __syncthreads per K-chunk. Staging = raw uint4.
#define HBUF 2560                       // uint32 per buffer (128*20)
#define GEMM_SMEM (4*HBUF*4)            // 40960 B

struct GemmP {
    const __half* A;
    const __half* W[3];     // transposed [N][K] fp16
    const float* bias[3];
    void*        C[3];
    const float* resid;
    int K, N;
};

template<int ACT, bool RESID, bool OUTH>
__global__ __launch_bounds__(512)
void gemm_fp16(GemmP p)
{
    extern __shared__ uint32_t sm32[];
    uint32_t* Asb = sm32;               // [2][128*20]
    uint32_t* Bsb = sm32 + 2*HBUF;      // [2][128*20]

    const int z = blockIdx.z;
    const __half* __restrict__ A     = p.A;
    const __half* __restrict__ W     = p.W[z];
    const float*  __restrict__ bias  = p.bias[z];
    const float*  __restrict__ resid = p.resid;
    const int K = p.K, N = p.N;
    const int m0 = blockIdx.y * 128, n0 = blockIdx.x * 128;

    const int tid  = threadIdx.x;
    const int warp = tid >> 5, lane = tid & 31;
    const int g  = lane >> 2, qd = lane & 3;
    const int wm = (warp >> 2) * 32;
    const int wn = (warp & 3)  * 32;

    // both loaders: row = tid>>2 (0..127), qu = tid&3 -> one uint4 (8 halfs)
    const int ld_r = tid >> 2, ld_q = tid & 3;

    uint4 rav, rbv;
    float acc[2][4][4];
    #pragma unroll
    for (int i = 0; i < 2; i++)
        #pragma unroll
        for (int j = 0; j < 4; j++)
            #pragma unroll
            for (int u = 0; u < 4; u++) acc[i][j][u] = 0.f;

    const int nk = K >> 5;

    rav = *(const uint4*)&A[(size_t)(m0 + ld_r) * K + ld_q*8];
    rbv = *(const uint4*)&W[(size_t)(n0 + ld_r) * K + ld_q*8];
    *(uint4*)&Asb[ld_r*20 + ld_q*4] = rav;
    *(uint4*)&Bsb[ld_r*20 + ld_q*4] = rbv;
    __syncthreads();

    if (nk > 1) {
        rav = *(const uint4*)&A[(size_t)(m0 + ld_r) * K + 32 + ld_q*8];
        rbv = *(const uint4*)&W[(size_t)(n0 + ld_r) * K + 32 + ld_q*8];
    }

    for (int kt = 0; kt < nk; kt++) {
        const uint32_t* As = Asb + (kt & 1) * HBUF;
        const uint32_t* Bs = Bsb + (kt & 1) * HBUF;

        #pragma unroll
        for (int s = 0; s < 2; s++) {
            const int pb = s * 8;
            uint32_t afr[2][4], bfr[4][2];
            #pragma unroll
            for (int mi = 0; mi < 2; mi++) {
                const int m_ = wm + mi*16 + g;
                afr[mi][0] = As[ m_     *20 + pb + qd];
                afr[mi][1] = As[(m_ + 8)*20 + pb + qd];
                afr[mi][2] = As[ m_     *20 + pb + qd + 4];
                afr[mi][3] = As[(m_ + 8)*20 + pb + qd + 4];
            }
            #pragma unroll
            for (int ni = 0; ni < 4; ni++) {
                const int n_ = wn + ni*8 + g;
                bfr[ni][0] = Bs[n_*20 + pb + qd];
                bfr[ni][1] = Bs[n_*20 + pb + qd + 4];
            }
            #pragma unroll
            for (int mi = 0; mi < 2; mi++)
                #pragma unroll
                for (int ni = 0; ni < 4; ni++)
                    mma16(acc[mi][ni], afr[mi], bfr[ni]);
        }

        if (kt + 1 < nk) {
            uint32_t* Asw = Asb + ((kt + 1) & 1) * HBUF;
            uint32_t* Bsw = Bsb + ((kt + 1) & 1) * HBUF;
            *(uint4*)&Asw[ld_r*20 + ld_q*4] = rav;
            *(uint4*)&Bsw[ld_r*20 + ld_q*4] = rbv;
            if (kt + 2 < nk) {
                const int k0 = (kt + 2) << 5;
                rav = *(const uint4*)&A[(size_t)(m0 + ld_r) * K + k0 + ld_q*8];
                rbv = *(const uint4*)&W[(size_t)(n0 + ld_r) * K + k0 + ld_q*8];
            }
            __syncthreads();
        }
    }

    #pragma unroll
    for (int mi = 0; mi < 2; mi++) {
        const int r0 = m0 + wm + mi*16 + g;
        #pragma unroll
        for (int ni = 0; ni < 4; ni++) {
            const int c0 = n0 + wn + ni*8 + qd*2;
            const float2 bv = *(const float2*)&bias[c0];
            float v0 = acc[mi][ni][0] + bv.x;
            float v1 = acc[mi][ni][1] + bv.y;
            float v2 = acc[mi][ni][2] + bv.x;
            float v3 = acc[mi][ni][3] + bv.y;
            if (ACT == 1) {
                v0 = v0 / (1.0f + __expf(-v0));
                v1 = v1 / (1.0f + __expf(-v1));
                v2 = v2 / (1.0f + __expf(-v2));
                v3 = v3 / (1.0f + __expf(-v3));
            }
            if (RESID) {
                const float2 r1 = *(const float2*)&resid[(size_t)r0 * N + c0];
                const float2 r2 = *(const float2*)&resid[(size_t)(r0 + 8) * N + c0];
                v0 += r1.x; v1 += r1.y; v2 += r2.x; v3 += r2.y;
            }
            if (OUTH) {
                __half* Ch = (__half*)p.C[z];
                *(__half2*)&Ch[(size_t)r0       * N + c0] = __floats2half2_rn(v0, v1);
                *(__half2*)&Ch[(size_t)(r0 + 8) * N + c0] = __floats2half2_rn(v2, v3);
            } else {
                float* Cf = (float*)p.C[z];
                *(float2*)&Cf[(size_t)r0       * N + c0] = make_float2(v0, v1);
                *(float2*)&Cf[(size_t)(r0 + 8) * N + c0] = make_float2(v2, v3);
            }
        }
    }
}

// ---------------- weight transpose: W[K][N] fp32 -> WT[N][K] fp16 ------------
struct TEnt { const float* src; __half* dst; int K; int N; int t0; };
struct TTab { TEnt e[25]; int n; };

__global__ __launch_bounds__(256)
void transpose_w(TTab tab)
{
    __shared__ float tile[32][33];
    const int t = blockIdx.x;
    int mi = 0;
    #pragma unroll 1
    while (mi + 1 < tab.n && t >= tab.e[mi+1].t0) mi++;
    const TEnt e = tab.e[mi];
    const int lt  = t - e.t0;
    const int ntn = e.N >> 5;
    const int k0 = (lt / ntn) * 32, n0 = (lt % ntn) * 32;
    const int tid = threadIdx.x;
    #pragma unroll
    for (int i = 0; i < 4; i++) {
        const int idx = tid + 256*i;
        const int r = idx >> 5, c = idx & 31;
        tile[r][c] = e.src[(size_t)(k0 + r)*e.N + n0 + c];
    }
    __syncthreads();
    #pragma unroll
    for (int i = 0; i < 4; i++) {
        const int idx = tid + 256*i;
        const int r = idx >> 5, c = idx & 31;
        e.dst[(size_t)(n0 + r)*e.K + k0 + c] = __float2half_rn(tile[c][r]);
    }
}

// nf fp32 -> fp16
__global__ __launch_bounds__(256)
void cvt_nf(const float* __restrict__ src, __half* __restrict__ dst)
{
    const size_t i = ((size_t)blockIdx.x * blockDim.x + threadIdx.x) * 4;
    const float4 v = *(const float4*)&src[i];
    uint2 pk;
    pk.x = pack_h2(v.x, v.y);
    pk.y = pack_h2(v.z, v.w);
    *(uint2*)&dst[i] = pk;
}

// ---------------- fused flash attention v4 (all-fp16 I/O) --------------------
// Grid (T/64, B*H), 128 threads = 4 warps; warp owns 16 q-rows x full 64-col
// j tile, warp-local online softmax. fp16 m16n8k16 for QK^T and PV.
#define FLW_K  0
#define FLW_V  2304
#define FLW_P  4608
#define FLW_B  6912
#define FL_SMEM ((6912 + 2304)*4)   // 36864 B

__global__ __launch_bounds__(128, 4)
void flash_fp16(const __half* __restrict__ q, const __half* __restrict__ k,
                const __half* __restrict__ v,
                const __nv_bfloat16* __restrict__ biash,
                __half* __restrict__ o)
{
    extern __shared__ uint32_t smw[];
    uint32_t* KsU = smw + FLW_K;                 // [64][36] pairs along d
    uint32_t* VtU = smw + FLW_V;                 // [64][36] V^T pairs along j
    __nv_bfloat16* Bb = (__nv_bfloat16*)(smw + FLW_B);  // [4][16][72], stride 1152

    const int z = blockIdx.y;
    const int b = z >> 3, h = z & 7;
    const int i0 = blockIdx.x * 64;
    const __half* qp = q + (size_t)b*T_*D_ + h*HD_;
    const __half* kp = k + (size_t)b*T_*D_ + h*HD_;
    const __half* vp = v + (size_t)b*T_*D_ + h*HD_;
    const __nv_bfloat16* bp = biash + (size_t)z*T_*T_;

    const int tid = threadIdx.x;
    const int warp = tid >> 5, lane = tid & 31;
    const int g = lane >> 2, qd = lane & 3;
    const int slab = warp * 16;
    uint32_t* PwU = smw + FLW_P + warp * 576;    // [16][36]

    // stage Q (raw fp16 uint4) through KsU, lift this warp's frags to regs
    #pragma unroll
    for (int u = 0; u < 4; u++) {
        const int idx = u*128 + tid;             // 512 uint4
        const int r = idx >> 3, d8 = idx & 7;
        *(uint4*)&KsU[r*36 + d8*4] = *(const uint4*)&qp[(size_t)(i0 + r)*D_ + d8*8];
    }
    __syncthreads();
    uint32_t qf[4][4];
    #pragma unroll
    for (int s = 0; s < 4; s++) {
        const int mr = slab + g;
        qf[s][0] = KsU[ mr     *36 + 8*s + qd];
        qf[s][1] = KsU[(mr + 8)*36 + 8*s + qd];
        qf[s][2] = KsU[ mr     *36 + 8*s + qd + 4];
        qf[s][3] = KsU[(mr + 8)*36 + 8*s + qd + 4];
    }
    // first loop iteration begins with __syncthreads -> safe to reuse KsU

    float m0 = -1e30f, m1 = -1e30f, l0 = 0.f, l1 = 0.f;
    float oacc[8][4];
    #pragma unroll
    for (int n = 0; n < 8; n++)
        #pragma unroll
        for (int u = 0; u < 4; u++) oacc[n][u] = 0.f;

    for (int jt = 0; jt < T_/64; jt++) {
        const int j0 = jt * 64;
        __syncthreads();   // prev iter's PV done with VtU/PwU; Q frags in regs
        // K tile: raw copy
        #pragma unroll
        for (int u = 0; u < 4; u++) {
            const int idx = u*128 + tid;
            const int r = idx >> 3, d8 = idx & 7;
            *(uint4*)&KsU[r*36 + d8*4] = *(const uint4*)&kp[(size_t)(j0 + r)*D_ + d8*8];
        }
        // V tile transposed via byte_perm: VtU[d][jp] = (V[2jp][d], V[2jp+1][d])
        #pragma unroll
        for (int u = 0; u < 4; u++) {
            const int item = u*128 + tid;        // 512 items = 32 jp x 16 dg
            const int jp = item & 31, dg = item >> 5;
            const uint2 va = *(const uint2*)&vp[(size_t)(j0 + 2*jp    )*D_ + dg*4];
            const uint2 vb = *(const uint2*)&vp[(size_t)(j0 + 2*jp + 1)*D_ + dg*4];
            VtU[(dg*4+0)*36 + jp] = __byte_perm(va.x, vb.x, 0x5410);
            VtU[(dg*4+1)*36 + jp] = __byte_perm(va.x, vb.x, 0x7632);
            VtU[(dg*4+2)*36 + jp] = __byte_perm(va.y, vb.y, 0x5410);
            VtU[(dg*4+3)*36 + jp] = __byte_perm(va.y, vb.y, 0x7632);
        }
        // bias: 64 rows x 8 uint4, warp-slab stride 1152 bf16
        #pragma unroll
        for (int u = 0; u < 4; u++) {
            const int idx = u*128 + tid;
            const int br = idx >> 3, seg = idx & 7;
            *(uint4*)&Bb[(br >> 4)*1152 + (br & 15)*72 + seg*8] =
                *(const uint4*)&bp[(size_t)(i0 + br)*T_ + j0 + seg*8];
        }
        __syncthreads();

        // S = Q K^T
        float sacc[8][4];
        #pragma unroll
        for (int n = 0; n < 8; n++)
            #pragma unroll
            for (int u = 0; u < 4; u++) sacc[n][u] = 0.f;
        #pragma unroll
        for (int s = 0; s < 4; s++) {
            #pragma unroll
            for (int n = 0; n < 8; n++) {
                const int nr = n*8 + g;
                uint32_t bfr[2];
                bfr[0] = KsU[nr*36 + 8*s + qd];
                bfr[1] = KsU[nr*36 + 8*s + qd + 4];
                mma16(sacc[n], qf[s], bfr);
            }
        }

        // online softmax (log2 domain), warp-local
        float sv[8][4];
        float mx0 = -1e30f, mx1 = -1e30f;
        #pragma unroll
        for (int n = 0; n < 8; n++) {
            const int c = n*8 + qd*2;
            const float2 bv0 = __bfloat1622float2(*(const __nv_bfloat162*)&Bb[warp*1152 + g    *72 + c]);
            const float2 bv1 = __bfloat1622float2(*(const __nv_bfloat162*)&Bb[warp*1152 + (g+8)*72 + c]);
            sv[n][0] = fmaf(sacc[n][0], SC2_, bv0.x);
            sv[n][1] = fmaf(sacc[n][1], SC2_, bv0.y);
            sv[n][2] = fmaf(sacc[n][2], SC2_, bv1.x);
            sv[n][3] = fmaf(sacc[n][3], SC2_, bv1.y);
            mx0 = fmaxf(mx0, fmaxf(sv[n][0], sv[n][1]));
            mx1 = fmaxf(mx1, fmaxf(sv[n][2], sv[n][3]));
        }
        mx0 = fmaxf(mx0, __shfl_xor_sync(0xffffffffu, mx0, 1));
        mx0 = fmaxf(mx0, __shfl_xor_sync(0xffffffffu, mx0, 2));
        mx1 = fmaxf(mx1, __shfl_xor_sync(0xffffffffu, mx1, 1));
        mx1 = fmaxf(mx1, __shfl_xor_sync(0xffffffffu, mx1, 2));

        const float mn0 = fmaxf(m0, mx0), mn1 = fmaxf(m1, mx1);
        const float al0 = ex2(m0 - mn0),  al1 = ex2(m1 - mn1);
        float rs0 = 0.f, rs1 = 0.f;
        #pragma unroll
        for (int n = 0; n < 8; n++) {
            const float p0 = ex2(sv[n][0] - mn0);
            const float p1 = ex2(sv[n][1] - mn0);
            const float p2 = ex2(sv[n][2] - mn1);
            const float p3 = ex2(sv[n][3] - mn1);
            rs0 += p0 + p1; rs1 += p2 + p3;
            PwU[ g    *36 + n*4 + qd] = pack_h2(p0, p1);
            PwU[(g+8)*36 + n*4 + qd] = pack_h2(p2, p3);
            oacc[n][0] *= al0; oacc[n][1] *= al0;
            oacc[n][2] *= al1; oacc[n][3] *= al1;
        }
        rs0 += __shfl_xor_sync(0xffffffffu, rs0, 1);
        rs0 += __shfl_xor_sync(0xffffffffu, rs0, 2);
        rs1 += __shfl_xor_sync(0xffffffffu, rs1, 1);
        rs1 += __shfl_xor_sync(0xffffffffu, rs1, 2);
        l0 = l0*al0 + rs0;  m0 = mn0;
        l1 = l1*al1 + rs1;  m1 = mn1;

        __syncwarp();      // P rows warp-private; intra-warp visibility only

        // O += P @ V   (A = P [16][j], B = Vt [d][j])
        #pragma unroll
        for (int s = 0; s < 4; s++) {
            uint32_t afr[4];
            afr[0] = PwU[ g    *36 + 8*s + qd];
            afr[1] = PwU[(g+8)*36 + 8*s + qd];
            afr[2] = PwU[ g    *36 + 8*s + qd + 4];
            afr[3] = PwU[(g+8)*36 + 8*s + qd + 4];
            #pragma unroll
            for (int n = 0; n < 8; n++) {
                const int nr = n*8 + g;
                uint32_t bfr[2];
                bfr[0] = VtU[nr*36 + 8*s + qd];
                bfr[1] = VtU[nr*36 + 8*s + qd + 4];
                mma16(oacc[n], afr, bfr);
            }
        }
    }

    const float inv0 = 1.0f / l0, inv1 = 1.0f / l1;
    const size_t r0 = (size_t)b*T_ + i0 + slab + g;
    #pragma unroll
    for (int n = 0; n < 8; n++) {
        const int c = h*HD_ + n*8 + qd*2;
        *(__half2*)&o[ r0      * D_ + c] = __floats2half2_rn(oacc[n][0]*inv0, oacc[n][1]*inv0);
        *(__half2*)&o[(r0 + 8) * D_ + c] = __floats2half2_rn(oacc[n][2]*inv1, oacc[n][3]*inv1);
    }
}

// ---------------- embedding extras ------------------------------------------
__global__ void add_cent_kernel(float* __restrict__ h, const float* __restrict__ cent,
                                const float* __restrict__ cw, const float* __restrict__ cb)
{
    const int n = blockIdx.x, d = threadIdx.x;
    h[(size_t)n * D_ + d] += cent[n] * cw[d] + cb[d];
}

// biash = (edge_emb[et] + dist_emb[sp]) * log2(e) as bf16, via smem LUT.
__global__ __launch_bounds__(256)
void bias_kernel(const int* __restrict__ et, const int* __restrict__ sp,
                 const float* __restrict__ ee, const float* __restrict__ de,
                 __nv_bfloat16* __restrict__ bias)
{
    __shared__ uint4 lut[336];
    const int tid = threadIdx.x;
    for (int i = tid; i < 336; i += 256) {
        const int e = i / 21, s = i % 21;
        uint32_t w[4];
        #pragma unroll
        for (int p = 0; p < 4; p++) {
            __nv_bfloat16 lo = __float2bfloat16((ee[e*H_ + 2*p    ] + de[s*H_ + 2*p    ]) * LOG2E_);
            __nv_bfloat16 hi = __float2bfloat16((ee[e*H_ + 2*p + 1] + de[s*H_ + 2*p + 1]) * LOG2E_);
            __nv_bfloat162 pr = __halves2bfloat162(lo, hi);
            w[p] = *(uint32_t*)&pr;
        }
        lut[i] = make_uint4(w[0], w[1], w[2], w[3]);
    }
    __syncthreads();

    const size_t t4   = (size_t)blockIdx.x * blockDim.x + tid;  // B*T*T/4
    const size_t base = t4 * 4;
    const int4 e4 = *(const int4*)&et[base];
    int4 s4 = *(const int4*)&sp[base];
    s4.x = min(max(s4.x, 0), MD_); s4.y = min(max(s4.y, 0), MD_);
    s4.z = min(max(s4.z, 0), MD_); s4.w = min(max(s4.w, 0), MD_);
    const uint4 L0 = lut[e4.x*21 + s4.x];
    const uint4 L1 = lut[e4.y*21 + s4.y];
    const uint4 L2 = lut[e4.z*21 + s4.z];
    const uint4 L3 = lut[e4.w*21 + s4.w];
    const uint32_t* lw[4] = { (const uint32_t*)&L0, (const uint32_t*)&L1,
                              (const uint32_t*)&L2, (const uint32_t*)&L3 };
    const size_t j = base & (T_ - 1);
    const size_t i = (base >> 10) & (T_ - 1);
    const size_t b = base >> 20;
    #pragma unroll
    for (int hh = 0; hh < H_; hh++) {
        const int wi = hh >> 1, sh = (hh & 1) * 16;
        const uint32_t h0 = (lw[0][wi] >> sh) & 0xffffu;
        const uint32_t h1 = (lw[1][wi] >> sh) & 0xffffu;
        const uint32_t h2 = (lw[2][wi] >> sh) & 0xffffu;
        const uint32_t h3 = (lw[3][wi] >> sh) & 0xffffu;
        uint2 pk;
        pk.x = h0 | (h1 << 16);
        pk.y = h2 | (h3 << 16);
        *(uint2*)&bias[(((b*H_ + hh)*T_ + i)*T_) + j] = pk;
    }
}

// ---------------- layernorm (fp32 in, fp16 out) ------------------------------
__global__ __launch_bounds__(128)
void ln_kernel(const float* __restrict__ h, const float* __restrict__ w,
               const float* __restrict__ b, __half* __restrict__ out)
{
    __shared__ float red[8];
    const int t = threadIdx.x;
    const float* hp = h + (size_t)blockIdx.x * D_;
    const float4 vv = *(const float4*)&hp[t*4];
    float s  = vv.x + vv.y + vv.z + vv.w;
    float s2 = vv.x*vv.x + vv.y*vv.y + vv.z*vv.z + vv.w*vv.w;
    s  = warp_red_sum(s);
    s2 = warp_red_sum(s2);
    if ((t & 31) == 0) { red[t>>5] = s; red[4 + (t>>5)] = s2; }
    __syncthreads();
    s  = red[0] + red[1] + red[2] + red[3];
    s2 = red[4] + red[5] + red[6] + red[7];
    const float m   = s  * (1.0f / D_);
    const float var = s2 * (1.0f / D_) - m * m;
    const float r   = rsqrtf(var + 1e-5f);
    const float4 wv = *(const float4*)&w[t*4];
    const float4 bb = *(const float4*)&b[t*4];
    uint2 pk;
    pk.x = pack_h2((vv.x - m) * r * wv.x + bb.x, (vv.y - m) * r * wv.y + bb.y);
    pk.y = pack_h2((vv.z - m) * r * wv.z + bb.z, (vv.w - m) * r * wv.w + bb.w);
    *(uint2*)&out[(size_t)blockIdx.x * D_ + t*4] = pk;
}

// ---------------- host-side orchestration -----------------------------------
static inline void gemm1(const __half* A, const __half* WT, const float* bias,
                         const float* resid, void* C, int K, int N, int act, int outh)
{
    GemmP p;
    p.A = A;
    p.W[0] = p.W[1] = p.W[2] = WT;
    p.bias[0] = p.bias[1] = p.bias[2] = bias;
    p.C[0] = p.C[1] = p.C[2] = C;
    p.resid = resid;
    p.K = K; p.N = N;
    dim3 g(N / 128, NT_ / 128, 1);
    if (act == 1)        gemm_fp16<1,false,true ><<<g,512,GEMM_SMEM>>>(p);
    else if (resid)      gemm_fp16<0,true ,false><<<g,512,GEMM_SMEM>>>(p);
    else if (outh)       gemm_fp16<0,false,true ><<<g,512,GEMM_SMEM>>>(p);
    else                 gemm_fp16<0,false,false><<<g,512,GEMM_SMEM>>>(p);
}

extern "C" void kernel_launch(void* const* d_in, const int* in_sizes, int n_in,
                              void* d_out, int out_size)
{
    const float* nf     = (const float*)d_in[0];
    const float* cent   = (const float*)d_in[1];
    const int*   et     = (const int*)  d_in[2];
    const int*   sp     = (const int*)  d_in[3];
    const float* node_W = (const float*)d_in[4];
    const float* node_b = (const float*)d_in[5];
    const float* cent_W = (const float*)d_in[6];
    const float* cent_b = (const float*)d_in[7];
    const float* e_emb  = (const float*)d_in[8];
    const float* d_emb  = (const float*)d_in[9];
    const float* ln1w   = (const float*)d_in[10];
    const float* ln1b   = (const float*)d_in[11];
    const float* qW     = (const float*)d_in[12];
    const float* qb     = (const float*)d_in[13];
    const float* kW     = (const float*)d_in[14];
    const float* kb     = (const float*)d_in[15];
    const float* vW     = (const float*)d_in[16];
    const float* vb     = (const float*)d_in[17];
    const float* oW     = (const float*)d_in[18];
    const float* ob     = (const float*)d_in[19];
    const float* ln2w   = (const float*)d_in[20];
    const float* ln2b   = (const float*)d_in[21];
    const float* f1W    = (const float*)d_in[22];
    const float* f1b    = (const float*)d_in[23];
    const float* f2W    = (const float*)d_in[24];
    const float* f2b    = (const float*)d_in[25];

    float* h = (float*)d_out;

    __half *px, *pq, *pk, *pv, *po, *pffn, *pwt;
    __nv_bfloat16* pbias;
    cudaGetSymbolAddress((void**)&px,    g_x);
    cudaGetSymbolAddress((void**)&pq,    g_q);
    cudaGetSymbolAddress((void**)&pk,    g_k);
    cudaGetSymbolAddress((void**)&pv,    g_v);
    cudaGetSymbolAddress((void**)&po,    g_o);
    cudaGetSymbolAddress((void**)&pffn,  g_ffn);
    cudaGetSymbolAddress((void**)&pwt,   g_wt);
    cudaGetSymbolAddress((void**)&pbias, g_biash);

    cudaFuncSetAttribute(flash_fp16, cudaFuncAttributeMaxDynamicSharedMemorySize, FL_SMEM);

    // ---- transpose all weights into g_wt ([N][K] K-major, fp16) ----
    TTab tab;
    int te = 0, tiles = 0;
    auto addT = [&](const float* src, __half* dst, int K, int N) {
        tab.e[te].src = src; tab.e[te].dst = dst;
        tab.e[te].K = K; tab.e[te].N = N; tab.e[te].t0 = tiles;
        tiles += (K/32) * (N/32); te++;
    };
    addT(node_W, pwt, F_, D_);
    for (int l = 0; l < L_; l++) {
        __half* lb = pwt + WT_EMB_SZ + (size_t)l * WT_L_STRIDE;
        addT(qW + (size_t)l*D_*D_,   lb,                       D_,   D_);
        addT(kW + (size_t)l*D_*D_,   lb + D_*D_,               D_,   D_);
        addT(vW + (size_t)l*D_*D_,   lb + 2*D_*D_,             D_,   D_);
        addT(oW + (size_t)l*D_*D_,   lb + 3*D_*D_,             D_,   D_);
        addT(f1W + (size_t)l*D_*DFF_, lb + 4*D_*D_,            D_,   DFF_);
        addT(f2W + (size_t)l*DFF_*D_, lb + 4*D_*D_ + D_*DFF_,  DFF_, D_);
    }
    tab.n = te;
    transpose_w<<<tiles, 256>>>(tab);

    // embedding: convert nf to fp16 (into pq, free until QKV), then GEMM
    cvt_nf<<<(NT_*F_)/(256*4), 256>>>(nf, pq);
    gemm1(pq, pwt, node_b, nullptr, h, F_, D_, 0, 0);
    add_cent_kernel<<<NT_, D_>>>(h, cent, cent_W, cent_b);

    // Graphormer attention bias (layer-invariant), bf16, log2e pre-folded
    bias_kernel<<<(B_*T_*T_)/(256*4), 256>>>(et, sp, e_emb, d_emb, pbias);

    for (int l = 0; l < L_; l++) {
        __half* lb = pwt + WT_EMB_SZ + (size_t)l * WT_L_STRIDE;
        // x = LN1(h) -> fp16
        ln_kernel<<<NT_, 128>>>(h, ln1w + l*D_, ln1b + l*D_, px);
        // q,k,v in one batched launch (grid.z = 3), fp16 out
        {
            GemmP p;
            p.A = px;
            p.W[0] = lb;  p.W[1] = lb + D_*D_;  p.W[2] = lb + 2*D_*D_;
            p.bias[0] = qb + l*D_; p.bias[1] = kb + l*D_; p.bias[2] = vb + l*D_;
            p.C[0] = pq; p.C[1] = pk; p.C[2] = pv;
            p.resid = nullptr;
            p.K = D_; p.N = D_;
            gemm_fp16<0,false,true><<<dim3(D_/128, NT_/128, 3), 512, GEMM_SMEM>>>(p);
        }
        // fused attention: scores + softmax + AV, fp16 everywhere on-chip
        flash_fp16<<<dim3(T_/64, B_*H_), 128, FL_SMEM>>>(pq, pk, pv, pbias, po);
        // h += o @ oW + ob  (fp32 out + resid)
        gemm1(po, lb + 3*D_*D_, ob + l*D_, h, h, D_, D_, 0, 0);
        // FFN
        ln_kernel<<<NT_, 128>>>(h, ln2w + l*D_, ln2b + l*D_, px);
        gemm1(px,   lb + 4*D_*D_,            f1b + l*DFF_, nullptr, pffn, D_,   DFF_, 1, 1);
        gemm1(pffn, lb + 4*D_*D_ + D_*DFF_,  f2b + l*D_,   h,       h,    DFF_, D_,   0, 0);
    }
}

// round 17
// speedup vs baseline: 1.4781x; 1.0619x over previous
#include <cuda_runtime.h>
#include <cuda_bf16.h>
#include <cuda_fp16.h>
#include <math.h>
#include <stdint.h>

#define B_ 4
#define T_ 1024
#define F_ 128
#define D_ 512
#define H_ 8
#define L_ 4
#define DFF_ 2048
#define MD_ 20
#define HD_ 64
#define NT_ (B_*T_)
#define SCALE_ 0.125f
#define LOG2E_ 1.4426950408889634f
#define SC2_ (SCALE_*LOG2E_)

// ---------------- scratch (device globals: no allocations allowed) ----------
__device__ __half g_x  [NT_*(size_t)D_];
__device__ __half g_q  [NT_*(size_t)D_];
__device__ __half g_k  [NT_*(size_t)D_];
__device__ __half g_v  [NT_*(size_t)D_];
__device__ __half g_o  [NT_*(size_t)D_];
__device__ __half g_ffn[NT_*(size_t)DFF_];
__device__ __nv_bfloat16 g_biash[(size_t)B_*H_*T_*T_];   // bias * log2(e), bf16
#define WT_EMB_SZ   (F_*D_)                 // 65536
#define WT_L_STRIDE (4*D_*D_ + 2*D_*DFF_)   // 3145728
__device__ __half g_wt[WT_EMB_SZ + L_*(size_t)WT_L_STRIDE];   // ~25.3 MB

// ---------------- helpers ----------------------------------------------------
__device__ __forceinline__ float ex2(float x) {
    float y; asm("ex2.approx.f32 %0, %1;" : "=f"(y) : "f"(x)); return y;
}
__device__ __forceinline__ uint32_t pack_h2(float a, float b) {
    __half2 h = __floats2half2_rn(a, b);
    return *(uint32_t*)&h;
}
__device__ __forceinline__ uint32_t s2u(const void* p) {
    uint32_t a;
    asm("{ .reg .u64 t; cvta.to.shared.u64 t, %1; cvt.u32.u64 %0, t; }" : "=r"(a) : "l"(p));
    return a;
}
// fp16 mma m16n8k16, fp32 accumulate
__device__ __forceinline__ void mma16(float* d, const uint32_t* a, const uint32_t* b) {
    asm volatile(
      "mma.sync.aligned.m16n8k16.row.col.f32.f16.f16.f32 "
      "{%0,%1,%2,%3}, {%4,%5,%6,%7}, {%8,%9}, {%0,%1,%2,%3};\n"
      : "+f"(d[0]), "+f"(d[1]), "+f"(d[2]), "+f"(d[3])
      : "r"(a[0]), "r"(a[1]), "r"(a[2]), "r"(a[3]), "r"(b[0]), "r"(b[1]));
}
// ldmatrix x4: four 8x8 b16 tiles; lane supplies the row address
__device__ __forceinline__ void ldsm4(uint32_t* r, uint32_t addr) {
    asm volatile("ldmatrix.sync.aligned.m8n8.x4.shared.b16 {%0,%1,%2,%3}, [%4];"
        : "=r"(r[0]), "=r"(r[1]), "=r"(r[2]), "=r"(r[3]) : "r"(addr));
}
__device__ __forceinline__ float warp_red_sum(float v) {
    #pragma unroll
    for (int o = 16; o > 0; o >>= 1) v += __shfl_xor_sync(0xffffffffu, v, o);
    return v;
}

// ---------------- fp16 GEMM v5: ldmatrix frag loads --------------------------
// C[4096, N] = act(A[4096,K] @ W + bias) (+resid). A fp16 [M][K],
// W pre-transposed fp16 [N][K]. 128x128x32 tile, 512 threads, 32x32 warp tile.
// Smem uint32 [row][20]; frag loads via ldmatrix.x4 (conflict-free, pad-20).
#define HBUF 2560                       // uint32 per buffer (128*20)
#define GEMM_SMEM (4*HBUF*4)            // 40960 B

struct GemmP {
    const __half* A;
    const __half* W[3];
    const float* bias[3];
    void*        C[3];
    const float* resid;
    int K, N;
};

template<int ACT, bool RESID, bool OUTH>
__global__ __launch_bounds__(512)
void gemm_fp16(GemmP p)
{
    extern __shared__ uint32_t sm32[];
    const uint32_t sb = s2u(sm32);

    const int z = blockIdx.z;
    const __half* __restrict__ A     = p.A;
    const __half* __restrict__ W     = p.W[z];
    const float*  __restrict__ bias  = p.bias[z];
    const float*  __restrict__ resid = p.resid;
    const int K = p.K, N = p.N;
    const int m0 = blockIdx.y * 128, n0 = blockIdx.x * 128;

    const int tid  = threadIdx.x;
    const int warp = tid >> 5, lane = tid & 31;
    const int g  = lane >> 2, qd = lane & 3;
    const int wm = (warp >> 2) * 32;
    const int wn = (warp & 3)  * 32;

    const int ld_r = tid >> 2, ld_q = tid & 3;

    // ldmatrix lane addresses (bytes): A-style and B-style
    const int a_lr = (lane & 7) + ((lane >> 3) & 1) * 8;
    const int a_kh = (lane >> 4) * 4;
    const uint32_t aA0 = sb + (uint32_t)(((wm + a_lr)*20 + a_kh) * 4);
    const int b_lr = (lane & 7) + ((lane >> 4) ? 8 : 0);
    const int b_kh = ((lane >> 3) & 1) * 4;
    const uint32_t aB0 = sb + (uint32_t)(2*HBUF*4) + (uint32_t)(((wn + b_lr)*20 + b_kh) * 4);

    uint4 rav, rbv;
    float acc[2][4][4];
    #pragma unroll
    for (int i = 0; i < 2; i++)
        #pragma unroll
        for (int j = 0; j < 4; j++)
            #pragma unroll
            for (int u = 0; u < 4; u++) acc[i][j][u] = 0.f;

    const int nk = K >> 5;

    rav = *(const uint4*)&A[(size_t)(m0 + ld_r) * K + ld_q*8];
    rbv = *(const uint4*)&W[(size_t)(n0 + ld_r) * K + ld_q*8];
    *(uint4*)&sm32[ld_r*20 + ld_q*4]          = rav;
    *(uint4*)&sm32[2*HBUF + ld_r*20 + ld_q*4] = rbv;
    __syncthreads();

    if (nk > 1) {
        rav = *(const uint4*)&A[(size_t)(m0 + ld_r) * K + 32 + ld_q*8];
        rbv = *(const uint4*)&W[(size_t)(n0 + ld_r) * K + 32 + ld_q*8];
    }

    for (int kt = 0; kt < nk; kt++) {
        const uint32_t abase = aA0 + (kt & 1) * (HBUF*4);
        const uint32_t bbase = aB0 + (kt & 1) * (HBUF*4);

        #pragma unroll
        for (int s = 0; s < 2; s++) {
            const uint32_t off = s * 32;       // 8 words
            uint32_t afr[2][4], bq0[4], bq1[4];
            ldsm4(afr[0], abase + off);
            ldsm4(afr[1], abase + off + 1280); // +16 rows * 20 words * 4B
            ldsm4(bq0,    bbase + off);
            ldsm4(bq1,    bbase + off + 1280);
            #pragma unroll
            for (int mi = 0; mi < 2; mi++) {
                mma16(acc[mi][0], afr[mi], &bq0[0]);
                mma16(acc[mi][1], afr[mi], &bq0[2]);
                mma16(acc[mi][2], afr[mi], &bq1[0]);
                mma16(acc[mi][3], afr[mi], &bq1[2]);
            }
        }

        if (kt + 1 < nk) {
            uint32_t* Asw = sm32 + ((kt + 1) & 1) * HBUF;
            uint32_t* Bsw = sm32 + 2*HBUF + ((kt + 1) & 1) * HBUF;
            *(uint4*)&Asw[ld_r*20 + ld_q*4] = rav;
            *(uint4*)&Bsw[ld_r*20 + ld_q*4] = rbv;
            if (kt + 2 < nk) {
                const int k0 = (kt + 2) << 5;
                rav = *(const uint4*)&A[(size_t)(m0 + ld_r) * K + k0 + ld_q*8];
                rbv = *(const uint4*)&W[(size_t)(n0 + ld_r) * K + k0 + ld_q*8];
            }
            __syncthreads();
        }
    }

    #pragma unroll
    for (int mi = 0; mi < 2; mi++) {
        const int r0 = m0 + wm + mi*16 + g;
        #pragma unroll
        for (int ni = 0; ni < 4; ni++) {
            const int c0 = n0 + wn + ni*8 + qd*2;
            const float2 bv = *(const float2*)&bias[c0];
            float v0 = acc[mi][ni][0] + bv.x;
            float v1 = acc[mi][ni][1] + bv.y;
            float v2 = acc[mi][ni][2] + bv.x;
            float v3 = acc[mi][ni][3] + bv.y;
            if (ACT == 1) {
                v0 = v0 / (1.0f + __expf(-v0));
                v1 = v1 / (1.0f + __expf(-v1));
                v2 = v2 / (1.0f + __expf(-v2));
                v3 = v3 / (1.0f + __expf(-v3));
            }
            if (RESID) {
                const float2 r1 = *(const float2*)&resid[(size_t)r0 * N + c0];
                const float2 r2 = *(const float2*)&resid[(size_t)(r0 + 8) * N + c0];
                v0 += r1.x; v1 += r1.y; v2 += r2.x; v3 += r2.y;
            }
            if (OUTH) {
                __half* Ch = (__half*)p.C[z];
                *(__half2*)&Ch[(size_t)r0       * N + c0] = __floats2half2_rn(v0, v1);
                *(__half2*)&Ch[(size_t)(r0 + 8) * N + c0] = __floats2half2_rn(v2, v3);
            } else {
                float* Cf = (float*)p.C[z];
                *(float2*)&Cf[(size_t)r0       * N + c0] = make_float2(v0, v1);
                *(float2*)&Cf[(size_t)(r0 + 8) * N + c0] = make_float2(v2, v3);
            }
        }
    }
}

// ---------------- weight transpose: W[K][N] fp32 -> WT[N][K] fp16 ------------
struct TEnt { const float* src; __half* dst; int K; int N; int t0; };
struct TTab { TEnt e[25]; int n; };

__global__ __launch_bounds__(256)
void transpose_w(TTab tab)
{
    __shared__ float tile[32][33];
    const int t = blockIdx.x;
    int mi = 0;
    #pragma unroll 1
    while (mi + 1 < tab.n && t >= tab.e[mi+1].t0) mi++;
    const TEnt e = tab.e[mi];
    const int lt  = t - e.t0;
    const int ntn = e.N >> 5;
    const int k0 = (lt / ntn) * 32, n0 = (lt % ntn) * 32;
    const int tid = threadIdx.x;
    #pragma unroll
    for (int i = 0; i < 4; i++) {
        const int idx = tid + 256*i;
        const int r = idx >> 5, c = idx & 31;
        tile[r][c] = e.src[(size_t)(k0 + r)*e.N + n0 + c];
    }
    __syncthreads();
    #pragma unroll
    for (int i = 0; i < 4; i++) {
        const int idx = tid + 256*i;
        const int r = idx >> 5, c = idx & 31;
        e.dst[(size_t)(n0 + r)*e.K + k0 + c] = __float2half_rn(tile[c][r]);
    }
}

// nf fp32 -> fp16
__global__ __launch_bounds__(256)
void cvt_nf(const float* __restrict__ src, __half* __restrict__ dst)
{
    const size_t i = ((size_t)blockIdx.x * blockDim.x + threadIdx.x) * 4;
    const float4 v = *(const float4*)&src[i];
    uint2 pk;
    pk.x = pack_h2(v.x, v.y);
    pk.y = pack_h2(v.z, v.w);
    *(uint2*)&dst[i] = pk;
}

// ---------------- fused flash attention v5 (fp16 mma + ldmatrix) -------------
#define FLW_K  0
#define FLW_V  2304
#define FLW_P  4608
#define FLW_B  6912
#define FL_SMEM ((6912 + 2304)*4)   // 36864 B

__global__ __launch_bounds__(128, 4)
void flash_fp16(const __half* __restrict__ q, const __half* __restrict__ k,
                const __half* __restrict__ v,
                const __nv_bfloat16* __restrict__ biash,
                __half* __restrict__ o)
{
    extern __shared__ uint32_t smw[];
    uint32_t* KsU = smw + FLW_K;                 // [64][36] pairs along d
    uint32_t* VtU = smw + FLW_V;                 // [64][36] V^T pairs along j
    __nv_bfloat16* Bb = (__nv_bfloat16*)(smw + FLW_B);  // [4][16][72], stride 1152

    const int z = blockIdx.y;
    const int b = z >> 3, h = z & 7;
    const int i0 = blockIdx.x * 64;
    const __half* qp = q + (size_t)b*T_*D_ + h*HD_;
    const __half* kp = k + (size_t)b*T_*D_ + h*HD_;
    const __half* vp = v + (size_t)b*T_*D_ + h*HD_;
    const __nv_bfloat16* bp = biash + (size_t)z*T_*T_;

    const int tid = threadIdx.x;
    const int warp = tid >> 5, lane = tid & 31;
    const int g = lane >> 2, qd = lane & 3;
    const int slab = warp * 16;
    uint32_t* PwU = smw + FLW_P + warp * 576;    // [16][36]

    // ldmatrix lane addresses
    const uint32_t sbF = s2u(smw);
    const int a_lr = (lane & 7) + ((lane >> 3) & 1) * 8;
    const int a_kh = (lane >> 4) * 4;
    const int b_lr = (lane & 7) + ((lane >> 4) ? 8 : 0);
    const int b_kh = ((lane >> 3) & 1) * 4;
    const uint32_t aQ = sbF + (uint32_t)(((slab + a_lr)*36 + a_kh) * 4);            // KsU A-style
    const uint32_t aK = sbF + (uint32_t)((b_lr*36 + b_kh) * 4);                     // KsU B-style (+pn*16 rows)
    const uint32_t aV = sbF + (uint32_t)(FLW_V*4) + (uint32_t)((b_lr*36 + b_kh) * 4);
    const uint32_t aP = sbF + (uint32_t)(FLW_P*4 + warp*576*4) + (uint32_t)((a_lr*36 + a_kh) * 4);

    // stage Q (raw fp16 uint4) through KsU, lift this warp's frags to regs
    #pragma unroll
    for (int u = 0; u < 4; u++) {
        const int idx = u*128 + tid;             // 512 uint4
        const int r = idx >> 3, d8 = idx & 7;
        *(uint4*)&KsU[r*36 + d8*4] = *(const uint4*)&qp[(size_t)(i0 + r)*D_ + d8*8];
    }
    __syncthreads();
    uint32_t qf[4][4];
    #pragma unroll
    for (int s = 0; s < 4; s++) ldsm4(qf[s], aQ + s*32);
    // first loop iteration begins with __syncthreads -> safe to reuse KsU

    float m0 = -1e30f, m1 = -1e30f, l0 = 0.f, l1 = 0.f;
    float oacc[8][4];
    #pragma unroll
    for (int n = 0; n < 8; n++)
        #pragma unroll
        for (int u = 0; u < 4; u++) oacc[n][u] = 0.f;

    for (int jt = 0; jt < T_/64; jt++) {
        const int j0 = jt * 64;
        __syncthreads();   // prev iter's PV done with VtU/PwU; Q frags in regs
        // K tile: raw copy
        #pragma unroll
        for (int u = 0; u < 4; u++) {
            const int idx = u*128 + tid;
            const int r = idx >> 3, d8 = idx & 7;
            *(uint4*)&KsU[r*36 + d8*4] = *(const uint4*)&kp[(size_t)(j0 + r)*D_ + d8*8];
        }
        // V tile transposed via byte_perm
        #pragma unroll
        for (int u = 0; u < 4; u++) {
            const int item = u*128 + tid;
            const int jp = item & 31, dg = item >> 5;
            const uint2 va = *(const uint2*)&vp[(size_t)(j0 + 2*jp    )*D_ + dg*4];
            const uint2 vb = *(const uint2*)&vp[(size_t)(j0 + 2*jp + 1)*D_ + dg*4];
            VtU[(dg*4+0)*36 + jp] = __byte_perm(va.x, vb.x, 0x5410);
            VtU[(dg*4+1)*36 + jp] = __byte_perm(va.x, vb.x, 0x7632);
            VtU[(dg*4+2)*36 + jp] = __byte_perm(va.y, vb.y, 0x5410);
            VtU[(dg*4+3)*36 + jp] = __byte_perm(va.y, vb.y, 0x7632);
        }
        // bias: 64 rows x 8 uint4, warp-slab stride 1152 bf16
        #pragma unroll
        for (int u = 0; u < 4; u++) {
            const int idx = u*128 + tid;
            const int br = idx >> 3, seg = idx & 7;
            *(uint4*)&Bb[(br >> 4)*1152 + (br & 15)*72 + seg*8] =
                *(const uint4*)&bp[(size_t)(i0 + br)*T_ + j0 + seg*8];
        }
        __syncthreads();

        // S = Q K^T  (ldmatrix K frags: 4 quads of 2 n-blocks)
        float sacc[8][4];
        #pragma unroll
        for (int n = 0; n < 8; n++)
            #pragma unroll
            for (int u = 0; u < 4; u++) sacc[n][u] = 0.f;
        #pragma unroll
        for (int s = 0; s < 4; s++) {
            #pragma unroll
            for (int pn = 0; pn < 4; pn++) {
                uint32_t bq[4];
                ldsm4(bq, aK + (uint32_t)((pn*16*36)*4) + s*32);
                mma16(sacc[2*pn    ], qf[s], &bq[0]);
                mma16(sacc[2*pn + 1], qf[s], &bq[2]);
            }
        }

        // online softmax (log2 domain), warp-local
        float sv[8][4];
        float mx0 = -1e30f, mx1 = -1e30f;
        #pragma unroll
        for (int n = 0; n < 8; n++) {
            const int c = n*8 + qd*2;
            const float2 bv0 = __bfloat1622float2(*(const __nv_bfloat162*)&Bb[warp*1152 + g    *72 + c]);
            const float2 bv1 = __bfloat1622float2(*(const __nv_bfloat162*)&Bb[warp*1152 + (g+8)*72 + c]);
            sv[n][0] = fmaf(sacc[n][0], SC2_, bv0.x);
            sv[n][1] = fmaf(sacc[n][1], SC2_, bv0.y);
            sv[n][2] = fmaf(sacc[n][2], SC2_, bv1.x);
            sv[n][3] = fmaf(sacc[n][3], SC2_, bv1.y);
            mx0 = fmaxf(mx0, fmaxf(sv[n][0], sv[n][1]));
            mx1 = fmaxf(mx1, fmaxf(sv[n][2], sv[n][3]));
        }
        mx0 = fmaxf(mx0, __shfl_xor_sync(0xffffffffu, mx0, 1));
        mx0 = fmaxf(mx0, __shfl_xor_sync(0xffffffffu, mx0, 2));
        mx1 = fmaxf(mx1, __shfl_xor_sync(0xffffffffu, mx1, 1));
        mx1 = fmaxf(mx1, __shfl_xor_sync(0xffffffffu, mx1, 2));

        const float mn0 = fmaxf(m0, mx0), mn1 = fmaxf(m1, mx1);
        const float al0 = ex2(m0 - mn0),  al1 = ex2(m1 - mn1);
        float rs0 = 0.f, rs1 = 0.f;
        #pragma unroll
        for (int n = 0; n < 8; n++) {
            const float p0 = ex2(sv[n][0] - mn0);
            const float p1 = ex2(sv[n][1] - mn0);
            const float p2 = ex2(sv[n][2] - mn1);
            const float p3 = ex2(sv[n][3] - mn1);
            rs0 += p0 + p1; rs1 += p2 + p3;
            PwU[ g    *36 + n*4 + qd] = pack_h2(p0, p1);
            PwU[(g+8)*36 + n*4 + qd] = pack_h2(p2, p3);
            oacc[n][0] *= al0; oacc[n][1] *= al0;
            oacc[n][2] *= al1; oacc[n][3] *= al1;
        }
        rs0 += __shfl_xor_sync(0xffffffffu, rs0, 1);
        rs0 += __shfl_xor_sync(0xffffffffu, rs0, 2);
        rs1 += __shfl_xor_sync(0xffffffffu, rs1, 1);
        rs1 += __shfl_xor_sync(0xffffffffu, rs1, 2);
        l0 = l0*al0 + rs0;  m0 = mn0;
        l1 = l1*al1 + rs1;  m1 = mn1;

        __syncwarp();      // P rows warp-private; intra-warp visibility only

        // O += P @ V   (A = P via ldmatrix, B = Vt via ldmatrix)
        #pragma unroll
        for (int s = 0; s < 4; s++) {
            uint32_t afr[4];
            ldsm4(afr, aP + s*32);
            #pragma unroll
            for (int pn = 0; pn < 4; pn++) {
                uint32_t bq[4];
                ldsm4(bq, aV + (uint32_t)((pn*16*36)*4) + s*32);
                mma16(oacc[2*pn    ], afr, &bq[0]);
                mma16(oacc[2*pn + 1], afr, &bq[2]);
            }
        }
    }

    const float inv0 = 1.0f / l0, inv1 = 1.0f / l1;
    const size_t r0 = (size_t)b*T_ + i0 + slab + g;
    #pragma unroll
    for (int n = 0; n < 8; n++) {
        const int c = h*HD_ + n*8 + qd*2;
        *(__half2*)&o[ r0      * D_ + c] = __floats2half2_rn(oacc[n][0]*inv0, oacc[n][1]*inv0);
        *(__half2*)&o[(r0 + 8) * D_ + c] = __floats2half2_rn(oacc[n][2]*inv1, oacc[n][3]*inv1);
    }
}

// ---------------- embedding extras ------------------------------------------
__global__ void add_cent_kernel(float* __restrict__ h, const float* __restrict__ cent,
                                const float* __restrict__ cw, const float* __restrict__ cb)
{
    const int n = blockIdx.x, d = threadIdx.x;
    h[(size_t)n * D_ + d] += cent[n] * cw[d] + cb[d];
}

// biash = (edge_emb[et] + dist_emb[sp]) * log2(e) as bf16, via smem LUT.
__global__ __launch_bounds__(256)
void bias_kernel(const int* __restrict__ et, const int* __restrict__ sp,
                 const float* __restrict__ ee, const float* __restrict__ de,
                 __nv_bfloat16* __restrict__ bias)
{
    __shared__ uint4 lut[336];
    const int tid = threadIdx.x;
    for (int i = tid; i < 336; i += 256) {
        const int e = i / 21, s = i % 21;
        uint32_t w[4];
        #pragma unroll
        for (int p = 0; p < 4; p++) {
            __nv_bfloat16 lo = __float2bfloat16((ee[e*H_ + 2*p    ] + de[s*H_ + 2*p    ]) * LOG2E_);
            __nv_bfloat16 hi = __float2bfloat16((ee[e*H_ + 2*p + 1] + de[s*H_ + 2*p + 1]) * LOG2E_);
            __nv_bfloat162 pr = __halves2bfloat162(lo, hi);
            w[p] = *(uint32_t*)&pr;
        }
        lut[i] = make_uint4(w[0], w[1], w[2], w[3]);
    }
    __syncthreads();

    const size_t t4   = (size_t)blockIdx.x * blockDim.x + tid;
    const size_t base = t4 * 4;
    const int4 e4 = *(const int4*)&et[base];
    int4 s4 = *(const int4*)&sp[base];
    s4.x = min(max(s4.x, 0), MD_); s4.y = min(max(s4.y, 0), MD_);
    s4.z = min(max(s4.z, 0), MD_); s4.w = min(max(s4.w, 0), MD_);
    const uint4 L0 = lut[e4.x*21 + s4.x];
    const uint4 L1 = lut[e4.y*21 + s4.y];
    const uint4 L2 = lut[e4.z*21 + s4.z];
    const uint4 L3 = lut[e4.w*21 + s4.w];
    const uint32_t* lw[4] = { (const uint32_t*)&L0, (const uint32_t*)&L1,
                              (const uint32_t*)&L2, (const uint32_t*)&L3 };
    const size_t j = base & (T_ - 1);
    const size_t i = (base >> 10) & (T_ - 1);
    const size_t b = base >> 20;
    #pragma unroll
    for (int hh = 0; hh < H_; hh++) {
        const int wi = hh >> 1, sh = (hh & 1) * 16;
        const uint32_t h0 = (lw[0][wi] >> sh) & 0xffffu;
        const uint32_t h1 = (lw[1][wi] >> sh) & 0xffffu;
        const uint32_t h2 = (lw[2][wi] >> sh) & 0xffffu;
        const uint32_t h3 = (lw[3][wi] >> sh) & 0xffffu;
        uint2 pk;
        pk.x = h0 | (h1 << 16);
        pk.y = h2 | (h3 << 16);
        *(uint2*)&bias[(((b*H_ + hh)*T_ + i)*T_) + j] = pk;
    }
}

// ---------------- layernorm (fp32 in, fp16 out) ------------------------------
__global__ __launch_bounds__(128)
void ln_kernel(const float* __restrict__ h, const float* __restrict__ w,
               const float* __restrict__ b, __half* __restrict__ out)
{
    __shared__ float red[8];
    const int t = threadIdx.x;
    const float* hp = h + (size_t)blockIdx.x * D_;
    const float4 vv = *(const float4*)&hp[t*4];
    float s  = vv.x + vv.y + vv.z + vv.w;
    float s2 = vv.x*vv.x + vv.y*vv.y + vv.z*vv.z + vv.w*vv.w;
    s  = warp_red_sum(s);
    s2 = warp_red_sum(s2);
    if ((t & 31) == 0) { red[t>>5] = s; red[4 + (t>>5)] = s2; }
    __syncthreads();
    s  = red[0] + red[1] + red[2] + red[3];
    s2 = red[4] + red[5] + red[6] + red[7];
    const float m   = s  * (1.0f / D_);
    const float var = s2 * (1.0f / D_) - m * m;
    const float r   = rsqrtf(var + 1e-5f);
    const float4 wv = *(const float4*)&w[t*4];
    const float4 bb = *(const float4*)&b[t*4];
    uint2 pk;
    pk.x = pack_h2((vv.x - m) * r * wv.x + bb.x, (vv.y - m) * r * wv.y + bb.y);
    pk.y = pack_h2((vv.z - m) * r * wv.z + bb.z, (vv.w - m) * r * wv.w + bb.w);
    *(uint2*)&out[(size_t)blockIdx.x * D_ + t*4] = pk;
}

// ---------------- host-side orchestration -----------------------------------
static inline void gemm1(const __half* A, const __half* WT, const float* bias,
                         const float* resid, void* C, int K, int N, int act, int outh)
{
    GemmP p;
    p.A = A;
    p.W[0] = p.W[1] = p.W[2] = WT;
    p.bias[0] = p.bias[1] = p.bias[2] = bias;
    p.C[0] = p.C[1] = p.C[2] = C;
    p.resid = resid;
    p.K = K; p.N = N;
    dim3 g(N / 128, NT_ / 128, 1);
    if (act == 1)        gemm_fp16<1,false,true ><<<g,512,GEMM_SMEM>>>(p);
    else if (resid)      gemm_fp16<0,true ,false><<<g,512,GEMM_SMEM>>>(p);
    else if (outh)       gemm_fp16<0,false,true ><<<g,512,GEMM_SMEM>>>(p);
    else                 gemm_fp16<0,false,false><<<g,512,GEMM_SMEM>>>(p);
}

extern "C" void kernel_launch(void* const* d_in, const int* in_sizes, int n_in,
                              void* d_out, int out_size)
{
    const float* nf     = (const float*)d_in[0];
    const float* cent   = (const float*)d_in[1];
    const int*   et     = (const int*)  d_in[2];
    const int*   sp     = (const int*)  d_in[3];
    const float* node_W = (const float*)d_in[4];
    const float* node_b = (const float*)d_in[5];
    const float* cent_W = (const float*)d_in[6];
    const float* cent_b = (const float*)d_in[7];
    const float* e_emb  = (const float*)d_in[8];
    const float* d_emb  = (const float*)d_in[9];
    const float* ln1w   = (const float*)d_in[10];
    const float* ln1b   = (const float*)d_in[11];
    const float* qW     = (const float*)d_in[12];
    const float* qb     = (const float*)d_in[13];
    const float* kW     = (const float*)d_in[14];
    const float* kb     = (const float*)d_in[15];
    const float* vW     = (const float*)d_in[16];
    const float* vb     = (const float*)d_in[17];
    const float* oW     = (const float*)d_in[18];
    const float* ob     = (const float*)d_in[19];
    const float* ln2w   = (const float*)d_in[20];
    const float* ln2b   = (const float*)d_in[21];
    const float* f1W    = (const float*)d_in[22];
    const float* f1b    = (const float*)d_in[23];
    const float* f2W    = (const float*)d_in[24];
    const float* f2b    = (const float*)d_in[25];

    float* h = (float*)d_out;

    __half *px, *pq, *pk, *pv, *po, *pffn, *pwt;
    __nv_bfloat16* pbias;
    cudaGetSymbolAddress((void**)&px,    g_x);
    cudaGetSymbolAddress((void**)&pq,    g_q);
    cudaGetSymbolAddress((void**)&pk,    g_k);
    cudaGetSymbolAddress((void**)&pv,    g_v);
    cudaGetSymbolAddress((void**)&po,    g_o);
    cudaGetSymbolAddress((void**)&pffn,  g_ffn);
    cudaGetSymbolAddress((void**)&pwt,   g_wt);
    cudaGetSymbolAddress((void**)&pbias, g_biash);

    cudaFuncSetAttribute(flash_fp16, cudaFuncAttributeMaxDynamicSharedMemorySize, FL_SMEM);

    // ---- transpose all weights into g_wt ([N][K] K-major, fp16) ----
    TTab tab;
    int te = 0, tiles = 0;
    auto addT = [&](const float* src, __half* dst, int K, int N) {
        tab.e[te].src = src; tab.e[te].dst = dst;
        tab.e[te].K = K; tab.e[te].N = N; tab.e[te].t0 = tiles;
        tiles += (K/32) * (N/32); te++;
    };
    addT(node_W, pwt, F_, D_);
    for (int l = 0; l < L_; l++) {
        __half* lb = pwt + WT_EMB_SZ + (size_t)l * WT_L_STRIDE;
        addT(qW + (size_t)l*D_*D_,   lb,                       D_,   D_);
        addT(kW + (size_t)l*D_*D_,   lb + D_*D_,               D_,   D_);
        addT(vW + (size_t)l*D_*D_,   lb + 2*D_*D_,             D_,   D_);
        addT(oW + (size_t)l*D_*D_,   lb + 3*D_*D_,             D_,   D_);
        addT(f1W + (size_t)l*D_*DFF_, lb + 4*D_*D_,            D_,   DFF_);
        addT(f2W + (size_t)l*DFF_*D_, lb + 4*D_*D_ + D_*DFF_,  DFF_, D_);
    }
    tab.n = te;
    transpose_w<<<tiles, 256>>>(tab);

    // embedding: convert nf to fp16 (into pq, free until QKV), then GEMM
    cvt_nf<<<(NT_*F_)/(256*4), 256>>>(nf, pq);
    gemm1(pq, pwt, node_b, nullptr, h, F_, D_, 0, 0);
    add_cent_kernel<<<NT_, D_>>>(h, cent, cent_W, cent_b);

    // Graphormer attention bias (layer-invariant), bf16, log2e pre-folded
    bias_kernel<<<(B_*T_*T_)/(256*4), 256>>>(et, sp, e_emb, d_emb, pbias);

    for (int l = 0; l < L_; l++) {
        __half* lb = pwt + WT_EMB_SZ + (size_t)l * WT_L_STRIDE;
        // x = LN1(h) -> fp16
        ln_kernel<<<NT_, 128>>>(h, ln1w + l*D_, ln1b + l*D_, px);
        // q,k,v in one batched launch (grid.z = 3), fp16 out
        {
            GemmP p;
            p.A = px;
            p.W[0] = lb;  p.W[1] = lb + D_*D_;  p.W[2] = lb + 2*D_*D_;
            p.bias[0] = qb + l*D_; p.bias[1] = kb + l*D_; p.bias[2] = vb + l*D_;
            p.C[0] = pq; p.C[1] = pk; p.C[2] = pv;
            p.resid = nullptr;
            p.K = D_; p.N = D_;
            gemm_fp16<0,false,true><<<dim3(D_/128, NT_/128, 3), 512, GEMM_SMEM>>>(p);
        }
        // fused attention: scores + softmax + AV, fp16 everywhere on-chip
        flash_fp16<<<dim3(T_/64, B_*H_), 128, FL_SMEM>>>(pq, pk, pv, pbias, po);
        // h += o @ oW + ob  (fp32 out + resid)
        gemm1(po, lb + 3*D_*D_, ob + l*D_, h, h, D_, D_, 0, 0);
        // FFN
        ln_kernel<<<NT_, 128>>>(h, ln2w + l*D_, ln2b + l*D_, px);
        gemm1(px,   lb + 4*D_*D_,            f1b + l*DFF_, nullptr, pffn, D_,   DFF_, 1, 1);
        gemm1(pffn, lb + 4*D_*D_ + D_*DFF_,  f2b + l*D_,   h,       h,    DFF_, D_,   0, 0);
    }
}